// round 10
// baseline (speedup 1.0000x reference)
#include <cuda_runtime.h>
#include <cuda_fp16.h>
#include <cstdint>

#define B_   2
#define S_   2048
#define HID_ 4096
#define NH_  32
#define NKV_ 8
#define HD_  128

typedef __half f16;

// ---------------- device scratch ----------------
__device__ f16   g_hsh[(size_t)B_ * S_ * HID_];
__device__ f16   g_hsl[(size_t)B_ * S_ * HID_];
__device__ f16   g_w  [(size_t)(HID_ + 2 * NKV_ * HD_) * HID_];
__device__ f16   g_wd [(size_t)HID_ * HID_];
__device__ float g_qf [(size_t)B_ * NH_ * S_ * HD_];
__device__ float g_kf [(size_t)B_ * NKV_ * S_ * HD_];
__device__ f16   g_qh [(size_t)B_ * NH_ * S_ * HD_];
__device__ f16   g_ql [(size_t)B_ * NH_ * S_ * HD_];
__device__ f16   g_kh [(size_t)B_ * NKV_ * S_ * HD_];
__device__ f16   g_vh [(size_t)B_ * NKV_ * S_ * HD_];
__device__ f16   g_ch [(size_t)B_ * S_ * HID_];

// ---------------- helpers ----------------
__device__ __forceinline__ void cp16(void* dst, const void* src) {
    unsigned d = (unsigned)__cvta_generic_to_shared(dst);
    asm volatile("cp.async.cg.shared.global [%0], [%1], 16;\n" :: "r"(d), "l"(src));
}
__device__ __forceinline__ void cp_commit() { asm volatile("cp.async.commit_group;\n"); }
__device__ __forceinline__ void cp_wait0()  { asm volatile("cp.async.wait_group 0;\n"); }
__device__ __forceinline__ void cp_wait1()  { asm volatile("cp.async.wait_group 1;\n"); }

__device__ __forceinline__ void ldsm4(uint32_t* r, const void* p) {
    uint32_t a = (uint32_t)__cvta_generic_to_shared(p);
    asm volatile("ldmatrix.sync.aligned.m8n8.x4.shared.b16 {%0,%1,%2,%3}, [%4];\n"
        : "=r"(r[0]), "=r"(r[1]), "=r"(r[2]), "=r"(r[3]) : "r"(a));
}
__device__ __forceinline__ void ldsm4t(uint32_t* r, const void* p) {
    uint32_t a = (uint32_t)__cvta_generic_to_shared(p);
    asm volatile("ldmatrix.sync.aligned.m8n8.x4.trans.shared.b16 {%0,%1,%2,%3}, [%4];\n"
        : "=r"(r[0]), "=r"(r[1]), "=r"(r[2]), "=r"(r[3]) : "r"(a));
}

// fp16 mma, fp32 accumulate
__device__ __forceinline__ void mma16h(float* c, const uint32_t* a, uint32_t b0, uint32_t b1) {
    asm volatile(
        "mma.sync.aligned.m16n8k16.row.col.f32.f16.f16.f32 "
        "{%0,%1,%2,%3},{%4,%5,%6,%7},{%8,%9},{%0,%1,%2,%3};\n"
        : "+f"(c[0]), "+f"(c[1]), "+f"(c[2]), "+f"(c[3])
        : "r"(a[0]), "r"(a[1]), "r"(a[2]), "r"(a[3]), "r"(b0), "r"(b1));
}
// fp16 mma, fp16 accumulate (QK lo term)
__device__ __forceinline__ void mma16hh(uint32_t* c, const uint32_t* a, uint32_t b0, uint32_t b1) {
    asm volatile(
        "mma.sync.aligned.m16n8k16.row.col.f16.f16.f16.f16 "
        "{%0,%1},{%2,%3,%4,%5},{%6,%7},{%0,%1};\n"
        : "+r"(c[0]), "+r"(c[1])
        : "r"(a[0]), "r"(a[1]), "r"(a[2]), "r"(a[3]), "r"(b0), "r"(b1));
}

// fp16 packing
__device__ __forceinline__ uint32_t packh16(float e, float o) {
    __half2 t = __floats2half2_rn(e, o);
    return *reinterpret_cast<const uint32_t*>(&t);
}
__device__ __forceinline__ uint32_t packl16(float e, float o) {
    float he = __half2float(__float2half_rn(e));
    float ho = __half2float(__float2half_rn(o));
    return packh16(e - he, o - ho);
}
__device__ __forceinline__ void sstore16(f16* oh, f16* ol, int i, float v) {
    f16 h = __float2half_rn(v);
    oh[i] = h;
    ol[i] = __float2half_rn(v - __half2float(h));
}

// ---------------- fused split pass ----------
#define NHS_ (B_ * S_ * HID_)
#define NWQ_ (HID_ * HID_)
#define NWKV_ (2 * NKV_ * HD_ * HID_)

__global__ void split4_kernel(const float* __restrict__ hs, const float* __restrict__ Wq,
                              const float* __restrict__ Wkv, const float* __restrict__ Wd)
{
    int t = blockIdx.x * blockDim.x + threadIdx.x;
    const int q0 = NHS_ / 4, q1 = q0 + NWQ_ / 4, q2 = q1 + NWKV_ / 4;
    if (t < q0) {
        int i = t * 4;
        float4 x = *(const float4*)(hs + i);
        *(uint32_t*)(g_hsh + i)     = packh16(x.x, x.y);
        *(uint32_t*)(g_hsh + i + 2) = packh16(x.z, x.w);
        *(uint32_t*)(g_hsl + i)     = packl16(x.x, x.y);
        *(uint32_t*)(g_hsl + i + 2) = packl16(x.z, x.w);
    } else {
        const float* src;
        f16* dst;
        int i;
        if (t < q1)      { src = Wq;  dst = g_w;         i = (t - q0) * 4; }
        else if (t < q2) { src = Wkv; dst = g_w + NWQ_;  i = (t - q1) * 4; }
        else             { src = Wd;  dst = g_wd;        i = (t - q2) * 4; }
        float4 x = *(const float4*)(src + i);
        *(uint32_t*)(dst + i)     = packh16(x.x, x.y);
        *(uint32_t*)(dst + i + 2) = packh16(x.z, x.w);
    }
}

// ------------- NT GEMM: 512 thr, 128x256x32, fp16, selectable 1/2-pass -------
// Blocks with n0 <  nlo: 2-pass (a_hi*b + a_lo*b)
// Blocks with n0 >= nlo: 1-pass (a_hi*b only)
#define GBM 128
#define GBN 256
#define GBK 32
#define ARS 40
#define NSTG 3
#define AH_STG (GBM * ARS)
#define STGH ((2 * GBM + GBN) * ARS)
#define GSMEM (NSTG * STGH * 2)

__global__ __launch_bounds__(512, 1) void gemm_f16x2(
    const f16* __restrict__ Ah, const f16* __restrict__ Al,
    const f16* __restrict__ Wh,
    const float* __restrict__ bias, float* __restrict__ C,
    int N, int K, int nlo, int mode)
{
    extern __shared__ f16 smh[];

    int tid = threadIdx.x, lane = tid & 31, wid = tid >> 5;
    int g = lane >> 2, tg = lane & 3;
    int wm = (wid & 3) << 5;
    int wn = (wid >> 2) << 6;
    int m0 = blockIdx.y * GBM, n0 = blockIdx.x * GBN;
    const bool do_lo = (n0 < nlo);
    const f16* Abh = Ah + (size_t)m0 * K;
    const f16* Abl = Al + (size_t)m0 * K;
    const f16* Bbh = Wh + (size_t)n0 * K;

    float acc[2][8][4];
#pragma unroll
    for (int i = 0; i < 2; i++)
#pragma unroll
        for (int j = 0; j < 8; j++)
#pragma unroll
            for (int c = 0; c < 4; c++) acc[i][j][c] = 0.f;

    int nk = K / GBK;

    auto load_tile = [&](int kt, int s) {
        int k0 = kt * GBK;
        f16* ah = smh + s * STGH;
        f16* al = ah + AH_STG;
        f16* bh = al + AH_STG;
        {
            int row = tid >> 2, q = tid & 3;
            size_t go = (size_t)row * K + k0 + q * 8;
            cp16(&ah[row * ARS + q * 8], Abh + go);
            if (do_lo) cp16(&al[row * ARS + q * 8], Abl + go);
        }
#pragma unroll
        for (int i = 0; i < 2; i++) {
            int idx = tid + i * 512;
            int row = idx >> 2, q = idx & 3;
            size_t go = (size_t)row * K + k0 + q * 8;
            cp16(&bh[row * ARS + q * 8], Bbh + go);
        }
    };

    load_tile(0, 0); cp_commit();
    load_tile(1, 1); cp_commit();

    for (int kt = 0; kt < nk; kt++) {
        if (kt == nk - 1) cp_wait0(); else cp_wait1();
        __syncthreads();
        if (kt + 2 < nk) { load_tile(kt + 2, (kt + 2) % NSTG); cp_commit(); }

        int s = kt % NSTG;
        const f16* ah = smh + s * STGH;
        const f16* al = ah + AH_STG;
        const f16* bh = al + AH_STG;

#pragma unroll
        for (int k16 = 0; k16 < 2; k16++) {
            int kk = k16 * 16 + (lane >> 4) * 8;
            uint32_t fah[2][4], fal[2][4];
#pragma unroll
            for (int mi = 0; mi < 2; mi++) {
                int aoff = (wm + mi * 16 + (lane & 15)) * ARS + kk;
                ldsm4(fah[mi], ah + aoff);
                if (do_lo) ldsm4(fal[mi], al + aoff);
            }
#pragma unroll
            for (int njp = 0; njp < 4; njp++) {
                int boff = (wn + njp * 16 + (lane & 15)) * ARS + kk;
                uint32_t fbh[4];
                ldsm4(fbh, bh + boff);
#pragma unroll
                for (int mi = 0; mi < 2; mi++) {
                    mma16h(acc[mi][2 * njp],     fah[mi], fbh[0], fbh[2]);
                    mma16h(acc[mi][2 * njp + 1], fah[mi], fbh[1], fbh[3]);
                }
                if (do_lo) {
#pragma unroll
                    for (int mi = 0; mi < 2; mi++) {
                        mma16h(acc[mi][2 * njp],     fal[mi], fbh[0], fbh[2]);
                        mma16h(acc[mi][2 * njp + 1], fal[mi], fbh[1], fbh[3]);
                    }
                }
            }
        }
    }

    // epilogue
#pragma unroll
    for (int mi = 0; mi < 2; mi++) {
#pragma unroll
        for (int nj = 0; nj < 8; nj++) {
            int col = n0 + wn + nj * 8 + tg * 2;
#pragma unroll
            for (int half = 0; half < 2; half++) {
                int row = m0 + wm + mi * 16 + g + half * 8;
                float v0 = acc[mi][nj][half * 2], v1 = acc[mi][nj][half * 2 + 1];
                if (mode == 0) {
                    C[(size_t)row * N + col]     = v0 + bias[col];
                    C[(size_t)row * N + col + 1] = v1 + bias[col + 1];
                } else {
                    int bb = row >> 11, s2 = row & (S_ - 1);
                    if (col < HID_) {
                        int hh = col >> 7, d = col & 127;
                        size_t o = (((size_t)bb * NH_ + hh) * S_ + s2) * HD_ + d;
                        g_qf[o] = v0; g_qf[o + 1] = v1;
                    } else {
                        int n2 = col - HID_;
                        int kh = n2 >> 8, cc = n2 & 255;
                        if (cc < 128) {
                            size_t o = (((size_t)bb * NKV_ + kh) * S_ + s2) * HD_ + cc;
                            g_kf[o] = v0; g_kf[o + 1] = v1;
                        } else {
                            int d = cc - 128;
                            size_t o = (((size_t)bb * NKV_ + kh) * S_ + s2) * HD_ + d;
                            *(uint32_t*)(g_vh + o) = packh16(v0, v1);
                        }
                    }
                }
            }
        }
    }
}

// ---------------- RoPE + split (q -> f16 hi/lo, k -> f16) ----------------
__global__ void rope_split(const float* __restrict__ cosT, const float* __restrict__ sinT)
{
    int idx = blockIdx.x * blockDim.x + threadIdx.x;
    int d = idx & 63;
    int r = idx >> 6;
    int s = r & (S_ - 1);
    int hh = r >> 11;
    float c1 = cosT[s * HD_ + d],      s1 = sinT[s * HD_ + d];
    float c2 = cosT[s * HD_ + d + 64], s2 = sinT[s * HD_ + d + 64];
    if (hh < B_ * NH_) {
        const float* p = g_qf + (size_t)r * HD_;
        f16* oh = g_qh + (size_t)r * HD_;
        f16* ol = g_ql + (size_t)r * HD_;
        float x1 = p[d], x2 = p[d + 64];
        sstore16(oh, ol, d,      x1 * c1 - x2 * s1);
        sstore16(oh, ol, d + 64, x2 * c2 + x1 * s2);
    } else {
        size_t rr = (size_t)r - (size_t)B_ * NH_ * S_;
        const float* p = g_kf + rr * HD_;
        f16* ok = g_kh + rr * HD_;
        float x1 = p[d], x2 = p[d + 64];
        ok[d]      = __float2half_rn(x1 * c1 - x2 * s1);
        ok[d + 64] = __float2half_rn(x2 * c2 + x1 * s2);
    }
}

// ---------------- Flash attention, fp16 2-term ----------------
#define AQ 128
#define AK 64
#define RS_ 136
#define KVT (AK * RS_)
#define KVSTG (2 * KVT)
#define SBOFF (2 * AQ * RS_)
#define ASMEM ((SBOFF + 2 * KVSTG) * 2)

__global__ __launch_bounds__(256, 1) void attn_f16()
{
    extern __shared__ f16 smf[];
    f16* Qh = smf;
    f16* Ql = Qh + AQ * RS_;

    int qt = gridDim.x - 1 - blockIdx.x;
    int h = blockIdx.y, b = blockIdx.z;
    int tid = threadIdx.x, lane = tid & 31, wid = tid >> 5;
    int g = lane >> 2, tg = lane & 3;

    const f16* Qbh = g_qh + (((size_t)b * NH_ + h) * S_ + (size_t)qt * AQ) * HD_;
    const f16* Qbl = g_ql + (((size_t)b * NH_ + h) * S_ + (size_t)qt * AQ) * HD_;
    const f16* Kb  = g_kh + ((size_t)b * NKV_ + (h >> 2)) * S_ * HD_;
    const f16* Vb  = g_vh + ((size_t)b * NKV_ + (h >> 2)) * S_ * HD_;

#pragma unroll
    for (int i = 0; i < 8; i++) {
        int idx = tid + i * 256;
        int row = idx >> 4, q = idx & 15;
        size_t go = (size_t)row * HD_ + q * 8;
        cp16(&Qh[row * RS_ + q * 8], Qbh + go);
        cp16(&Ql[row * RS_ + q * 8], Qbl + go);
    }
    cp_commit();

    auto load_kv = [&](int kt, int s) {
        f16* base = smf + SBOFF + s * KVSTG;
#pragma unroll
        for (int i = 0; i < 4; i++) {
            int idx = tid + i * 256;
            int row = idx >> 4, q = idx & 15;
            size_t go = (size_t)(kt * AK + row) * HD_ + q * 8;
            int so = row * RS_ + q * 8;
            cp16(&base[so],       Kb + go);
            cp16(&base[KVT + so], Vb + go);
        }
    };

    float o[16][4];
#pragma unroll
    for (int j = 0; j < 16; j++)
#pragma unroll
        for (int c = 0; c < 4; c++) o[j][c] = 0.f;
    float m0 = -1e30f, m1 = -1e30f, l0 = 0.f, l1 = 0.f;
    const float scale = 0.08838834764831845f;
    int pr = wid * 16;

    int nkt = (qt + 1) * 2;
    load_kv(0, 0); cp_commit();

    for (int kt = 0; kt < nkt; kt++) {
        cp_wait0();
        __syncthreads();
        if (kt + 1 < nkt) { load_kv(kt + 1, (kt + 1) & 1); cp_commit(); }

        f16* Kh = smf + SBOFF + (kt & 1) * KVSTG;
        f16* Vh = Kh + KVT;

        float sf[8][4];
        uint32_t slo[8][2];
#pragma unroll
        for (int j = 0; j < 8; j++) {
            sf[j][0] = sf[j][1] = sf[j][2] = sf[j][3] = 0.f;
            slo[j][0] = slo[j][1] = 0u;
        }

#pragma unroll
        for (int k16 = 0; k16 < 8; k16++) {
            int kk = k16 * 16 + (lane >> 4) * 8;
            int aoff = (pr + (lane & 15)) * RS_ + kk;
            uint32_t fah[4], fal[4];
            ldsm4(fah, Qh + aoff);
            ldsm4(fal, Ql + aoff);
#pragma unroll
            for (int np2 = 0; np2 < 2; np2++) {
                uint32_t fb[2][4];
#pragma unroll
                for (int u = 0; u < 2; u++) {
                    int boff = ((np2 * 2 + u) * 16 + (lane & 15)) * RS_ + kk;
                    ldsm4(fb[u], Kh + boff);
                }
#pragma unroll
                for (int u = 0; u < 2; u++) {
                    int j = (np2 * 2 + u) * 2;
                    mma16h(sf[j],     fah, fb[u][0], fb[u][2]);
                    mma16h(sf[j + 1], fah, fb[u][1], fb[u][3]);
                }
#pragma unroll
                for (int u = 0; u < 2; u++) {
                    int j = (np2 * 2 + u) * 2;
                    mma16hh(slo[j],     fal, fb[u][0], fb[u][2]);
                    mma16hh(slo[j + 1], fal, fb[u][1], fb[u][3]);
                }
            }
        }
#pragma unroll
        for (int j = 0; j < 8; j++) {
            __half2 u0 = *reinterpret_cast<__half2*>(&slo[j][0]);
            __half2 u1 = *reinterpret_cast<__half2*>(&slo[j][1]);
            sf[j][0] += __low2float(u0);  sf[j][1] += __high2float(u0);
            sf[j][2] += __low2float(u1);  sf[j][3] += __high2float(u1);
        }

        int row0 = qt * AQ + wid * 16 + g;
        int colb = kt * AK + tg * 2;
        float mx0 = -1e30f, mx1 = -1e30f;
#pragma unroll
        for (int nj = 0; nj < 8; nj++) {
#pragma unroll
            for (int c = 0; c < 4; c++) {
                int col = colb + nj * 8 + (c & 1);
                int row = row0 + ((c & 2) ? 8 : 0);
                float v = sf[nj][c] * scale;
                if (col > row) v = -1e30f;
                sf[nj][c] = v;
                if (c < 2) mx0 = fmaxf(mx0, v); else mx1 = fmaxf(mx1, v);
            }
        }
        mx0 = fmaxf(mx0, __shfl_xor_sync(0xffffffffu, mx0, 1));
        mx0 = fmaxf(mx0, __shfl_xor_sync(0xffffffffu, mx0, 2));
        mx1 = fmaxf(mx1, __shfl_xor_sync(0xffffffffu, mx1, 1));
        mx1 = fmaxf(mx1, __shfl_xor_sync(0xffffffffu, mx1, 2));

        float mn0 = fmaxf(m0, mx0), mn1 = fmaxf(m1, mx1);
        float al0 = __expf(m0 - mn0), al1 = __expf(m1 - mn1);
        m0 = mn0; m1 = mn1;

        float rs0 = 0.f, rs1 = 0.f;
#pragma unroll
        for (int nj = 0; nj < 8; nj++) {
            float p0 = __expf(sf[nj][0] - mn0), p1 = __expf(sf[nj][1] - mn0);
            float p2 = __expf(sf[nj][2] - mn1), p3 = __expf(sf[nj][3] - mn1);
            sf[nj][0] = p0; sf[nj][1] = p1; sf[nj][2] = p2; sf[nj][3] = p3;
            rs0 += p0 + p1; rs1 += p2 + p3;
        }
        rs0 += __shfl_xor_sync(0xffffffffu, rs0, 1);
        rs0 += __shfl_xor_sync(0xffffffffu, rs0, 2);
        rs1 += __shfl_xor_sync(0xffffffffu, rs1, 1);
        rs1 += __shfl_xor_sync(0xffffffffu, rs1, 2);
        l0 = l0 * al0 + rs0;
        l1 = l1 * al1 + rs1;
#pragma unroll
        for (int j = 0; j < 16; j++) {
            o[j][0] *= al0; o[j][1] *= al0; o[j][2] *= al1; o[j][3] *= al1;
        }

#pragma unroll
        for (int t = 0; t < 4; t++) {
            uint32_t pah[4], pal[4];
            pah[0] = packh16(sf[2 * t][0], sf[2 * t][1]);
            pal[0] = packl16(sf[2 * t][0], sf[2 * t][1]);
            pah[1] = packh16(sf[2 * t][2], sf[2 * t][3]);
            pal[1] = packl16(sf[2 * t][2], sf[2 * t][3]);
            pah[2] = packh16(sf[2 * t + 1][0], sf[2 * t + 1][1]);
            pal[2] = packl16(sf[2 * t + 1][0], sf[2 * t + 1][1]);
            pah[3] = packh16(sf[2 * t + 1][2], sf[2 * t + 1][3]);
            pal[3] = packl16(sf[2 * t + 1][2], sf[2 * t + 1][3]);
#pragma unroll
            for (int dp = 0; dp < 4; dp++) {
                uint32_t fv[2][4];
#pragma unroll
                for (int u = 0; u < 2; u++) {
                    int dj = dp * 2 + u;
                    int voff = (t * 16 + (lane & 15)) * RS_ + dj * 16 + (lane >> 4) * 8;
                    ldsm4t(fv[u], Vh + voff);
                }
#pragma unroll
                for (int u = 0; u < 2; u++) {
                    int dj = dp * 2 + u;
                    mma16h(o[2 * dj],     pah, fv[u][0], fv[u][1]);
                    mma16h(o[2 * dj + 1], pah, fv[u][2], fv[u][3]);
                }
#pragma unroll
                for (int u = 0; u < 2; u++) {
                    int dj = dp * 2 + u;
                    mma16h(o[2 * dj],     pal, fv[u][0], fv[u][1]);
                    mma16h(o[2 * dj + 1], pal, fv[u][2], fv[u][3]);
                }
            }
        }
    }

    // epilogue: O/l -> ctx fp16 (hi only; GEMM2 is single-pass)
    float il0 = 1.f / l0, il1 = 1.f / l1;
    int row0 = qt * AQ + wid * 16 + g;
    size_t b0 = ((size_t)b * S_ + row0) * HID_ + (size_t)h * HD_;
    size_t b1 = b0 + (size_t)8 * HID_;
#pragma unroll
    for (int nj = 0; nj < 16; nj++) {
        int d = nj * 8 + tg * 2;
        *(uint32_t*)(g_ch + b0 + d) = packh16(o[nj][0] * il0, o[nj][1] * il0);
        *(uint32_t*)(g_ch + b1 + d) = packh16(o[nj][2] * il1, o[nj][3] * il1);
    }
}

// ---------------- launch ----------------
extern "C" void kernel_launch(void* const* d_in, const int* in_sizes, int n_in,
                              void* d_out, int out_size)
{
    const float* hs   = (const float*)d_in[0];
    const float* cosT = (const float*)d_in[2];
    const float* sinT = (const float*)d_in[3];
    const float* Wq   = (const float*)d_in[4];
    const float* Wkv  = (const float*)d_in[5];
    const float* Wd   = (const float*)d_in[6];
    const float* bd   = (const float*)d_in[7];
    float* out = (float*)d_out;

    cudaFuncSetAttribute(gemm_f16x2, cudaFuncAttributeMaxDynamicSharedMemorySize, GSMEM);
    cudaFuncSetAttribute(attn_f16, cudaFuncAttributeMaxDynamicSharedMemorySize, ASMEM);

    void *hsh, *hsl, *w, *wd, *ch;
    cudaGetSymbolAddress(&hsh, g_hsh);  cudaGetSymbolAddress(&hsl, g_hsl);
    cudaGetSymbolAddress(&w,   g_w);    cudaGetSymbolAddress(&wd,  g_wd);
    cudaGetSymbolAddress(&ch,  g_ch);

    const int total4 = (NHS_ + NWQ_ + NWKV_ + NWQ_) / 4;
    split4_kernel<<<total4 / 256, 256>>>(hs, Wq, Wkv, Wd);

    // GEMM1: q columns (n0 < 4096) 2-pass; k/v columns 1-pass
    gemm_f16x2<<<dim3((HID_ + 2 * NKV_ * HD_) / GBN, (B_ * S_) / GBM), 512, GSMEM>>>(
        (const f16*)hsh, (const f16*)hsl, (const f16*)w,
        bd, out, HID_ + 2 * NKV_ * HD_, HID_, HID_, 1);

    rope_split<<<(B_ * (NH_ + NKV_) * S_ * 64) / 256, 256>>>(cosT, sinT);

    attn_f16<<<dim3(S_ / AQ, NH_, B_), 256, ASMEM>>>();

    // GEMM2: single-pass (nlo = 0)
    gemm_f16x2<<<dim3(HID_ / GBN, (B_ * S_) / GBM), 512, GSMEM>>>(
        (const f16*)ch, (const f16*)ch, (const f16*)wd,
        bd, out, HID_, HID_, 0, 0);
}

// round 11
// speedup vs baseline: 1.7365x; 1.7365x over previous
#include <cuda_runtime.h>
#include <cuda_fp16.h>
#include <cstdint>

#define B_   2
#define S_   2048
#define HID_ 4096
#define NH_  32
#define NKV_ 8
#define HD_  128

typedef __half f16;

// ---------------- device scratch ----------------
__device__ f16   g_hsh[(size_t)B_ * S_ * HID_];
__device__ f16   g_hsl[(size_t)B_ * S_ * HID_];
__device__ f16   g_w  [(size_t)(HID_ + 2 * NKV_ * HD_) * HID_];
__device__ f16   g_wd [(size_t)HID_ * HID_];
__device__ float g_qf [(size_t)B_ * NH_ * S_ * HD_];
__device__ float g_kf [(size_t)B_ * NKV_ * S_ * HD_];
__device__ f16   g_qh [(size_t)B_ * NH_ * S_ * HD_];
__device__ f16   g_ql [(size_t)B_ * NH_ * S_ * HD_];
__device__ f16   g_kh [(size_t)B_ * NKV_ * S_ * HD_];
__device__ f16   g_vh [(size_t)B_ * NKV_ * S_ * HD_];
__device__ f16   g_ch [(size_t)B_ * S_ * HID_];

// ---------------- helpers ----------------
__device__ __forceinline__ void cp16(void* dst, const void* src) {
    unsigned d = (unsigned)__cvta_generic_to_shared(dst);
    asm volatile("cp.async.cg.shared.global [%0], [%1], 16;\n" :: "r"(d), "l"(src));
}
__device__ __forceinline__ void cp_commit() { asm volatile("cp.async.commit_group;\n"); }
__device__ __forceinline__ void cp_wait0()  { asm volatile("cp.async.wait_group 0;\n"); }
__device__ __forceinline__ void cp_wait1()  { asm volatile("cp.async.wait_group 1;\n"); }

__device__ __forceinline__ void ldsm4(uint32_t* r, const void* p) {
    uint32_t a = (uint32_t)__cvta_generic_to_shared(p);
    asm volatile("ldmatrix.sync.aligned.m8n8.x4.shared.b16 {%0,%1,%2,%3}, [%4];\n"
        : "=r"(r[0]), "=r"(r[1]), "=r"(r[2]), "=r"(r[3]) : "r"(a));
}
__device__ __forceinline__ void ldsm4t(uint32_t* r, const void* p) {
    uint32_t a = (uint32_t)__cvta_generic_to_shared(p);
    asm volatile("ldmatrix.sync.aligned.m8n8.x4.trans.shared.b16 {%0,%1,%2,%3}, [%4];\n"
        : "=r"(r[0]), "=r"(r[1]), "=r"(r[2]), "=r"(r[3]) : "r"(a));
}

__device__ __forceinline__ void mma16h(float* c, const uint32_t* a, uint32_t b0, uint32_t b1) {
    asm volatile(
        "mma.sync.aligned.m16n8k16.row.col.f32.f16.f16.f32 "
        "{%0,%1,%2,%3},{%4,%5,%6,%7},{%8,%9},{%0,%1,%2,%3};\n"
        : "+f"(c[0]), "+f"(c[1]), "+f"(c[2]), "+f"(c[3])
        : "r"(a[0]), "r"(a[1]), "r"(a[2]), "r"(a[3]), "r"(b0), "r"(b1));
}
__device__ __forceinline__ void mma16hh(uint32_t* c, const uint32_t* a, uint32_t b0, uint32_t b1) {
    asm volatile(
        "mma.sync.aligned.m16n8k16.row.col.f16.f16.f16.f16 "
        "{%0,%1},{%2,%3,%4,%5},{%6,%7},{%0,%1};\n"
        : "+r"(c[0]), "+r"(c[1])
        : "r"(a[0]), "r"(a[1]), "r"(a[2]), "r"(a[3]), "r"(b0), "r"(b1));
}

__device__ __forceinline__ uint32_t packh16(float e, float o) {
    __half2 t = __floats2half2_rn(e, o);
    return *reinterpret_cast<const uint32_t*>(&t);
}
__device__ __forceinline__ uint32_t packl16(float e, float o) {
    float he = __half2float(__float2half_rn(e));
    float ho = __half2float(__float2half_rn(o));
    return packh16(e - he, o - ho);
}
__device__ __forceinline__ void sstore16(f16* oh, f16* ol, int i, float v) {
    f16 h = __float2half_rn(v);
    oh[i] = h;
    ol[i] = __float2half_rn(v - __half2float(h));
}

// ---------------- fused split pass ----------
#define NHS_ (B_ * S_ * HID_)
#define NWQ_ (HID_ * HID_)
#define NWKV_ (2 * NKV_ * HD_ * HID_)

__global__ void split4_kernel(const float* __restrict__ hs, const float* __restrict__ Wq,
                              const float* __restrict__ Wkv, const float* __restrict__ Wd)
{
    int t = blockIdx.x * blockDim.x + threadIdx.x;
    const int q0 = NHS_ / 4, q1 = q0 + NWQ_ / 4, q2 = q1 + NWKV_ / 4;
    if (t < q0) {
        int i = t * 4;
        float4 x = *(const float4*)(hs + i);
        *(uint32_t*)(g_hsh + i)     = packh16(x.x, x.y);
        *(uint32_t*)(g_hsh + i + 2) = packh16(x.z, x.w);
        *(uint32_t*)(g_hsl + i)     = packl16(x.x, x.y);
        *(uint32_t*)(g_hsl + i + 2) = packl16(x.z, x.w);
    } else {
        const float* src;
        f16* dst;
        int i;
        if (t < q1)      { src = Wq;  dst = g_w;         i = (t - q0) * 4; }
        else if (t < q2) { src = Wkv; dst = g_w + NWQ_;  i = (t - q1) * 4; }
        else             { src = Wd;  dst = g_wd;        i = (t - q2) * 4; }
        float4 x = *(const float4*)(src + i);
        *(uint32_t*)(dst + i)     = packh16(x.x, x.y);
        *(uint32_t*)(dst + i + 2) = packh16(x.z, x.w);
    }
}

// ------------- NT GEMM: 512 thr, 128x256x32, fp16, templated -----------------
// MODE 0: C[row*N+col] = acc + bias[col]
// MODE 1: scatter q (cols are q columns, local col < 4096)
// MODE 2: scatter k/v (local col < 2048)
#define GBM 128
#define GBN 256
#define GBK 32
#define ARS 40
#define NSTG 3
#define AH_STG (GBM * ARS)
#define STGH ((2 * GBM + GBN) * ARS)
#define GSMEM (NSTG * STGH * 2)

template<int MODE, bool DO_LO>
__global__ __launch_bounds__(512, 1) void gemm_f16(
    const f16* __restrict__ Ah, const f16* __restrict__ Al,
    const f16* __restrict__ Wh,
    const float* __restrict__ bias, float* __restrict__ C,
    int N, int K)
{
    extern __shared__ f16 smh[];

    int tid = threadIdx.x, lane = tid & 31, wid = tid >> 5;
    int g = lane >> 2, tg = lane & 3;
    int wm = (wid & 3) << 5;
    int wn = (wid >> 2) << 6;
    int m0 = blockIdx.y * GBM, n0 = blockIdx.x * GBN;
    const f16* Abh = Ah + (size_t)m0 * K;
    const f16* Abl = Al + (size_t)m0 * K;
    const f16* Bbh = Wh + (size_t)n0 * K;

    float acc[2][8][4];
#pragma unroll
    for (int i = 0; i < 2; i++)
#pragma unroll
        for (int j = 0; j < 8; j++)
#pragma unroll
            for (int c = 0; c < 4; c++) acc[i][j][c] = 0.f;

    int nk = K / GBK;

    auto load_tile = [&](int kt, int s) {
        int k0 = kt * GBK;
        f16* ah = smh + s * STGH;
        f16* al = ah + AH_STG;
        f16* bh = al + AH_STG;
        {
            int row = tid >> 2, q = tid & 3;
            size_t go = (size_t)row * K + k0 + q * 8;
            cp16(&ah[row * ARS + q * 8], Abh + go);
            if (DO_LO) cp16(&al[row * ARS + q * 8], Abl + go);
        }
#pragma unroll
        for (int i = 0; i < 2; i++) {
            int idx = tid + i * 512;
            int row = idx >> 2, q = idx & 3;
            size_t go = (size_t)row * K + k0 + q * 8;
            cp16(&bh[row * ARS + q * 8], Bbh + go);
        }
    };

    load_tile(0, 0); cp_commit();
    load_tile(1, 1); cp_commit();

    for (int kt = 0; kt < nk; kt++) {
        if (kt == nk - 1) cp_wait0(); else cp_wait1();
        __syncthreads();
        if (kt + 2 < nk) { load_tile(kt + 2, (kt + 2) % NSTG); cp_commit(); }

        int s = kt % NSTG;
        const f16* ah = smh + s * STGH;
        const f16* al = ah + AH_STG;
        const f16* bh = al + AH_STG;

#pragma unroll
        for (int k16 = 0; k16 < 2; k16++) {
            int kk = k16 * 16 + (lane >> 4) * 8;
            uint32_t fah[2][4], fal[2][4];
#pragma unroll
            for (int mi = 0; mi < 2; mi++) {
                int aoff = (wm + mi * 16 + (lane & 15)) * ARS + kk;
                ldsm4(fah[mi], ah + aoff);
                if (DO_LO) ldsm4(fal[mi], al + aoff);
            }
#pragma unroll
            for (int njp = 0; njp < 4; njp++) {
                int boff = (wn + njp * 16 + (lane & 15)) * ARS + kk;
                uint32_t fbh[4];
                ldsm4(fbh, bh + boff);
#pragma unroll
                for (int mi = 0; mi < 2; mi++) {
                    mma16h(acc[mi][2 * njp],     fah[mi], fbh[0], fbh[2]);
                    mma16h(acc[mi][2 * njp + 1], fah[mi], fbh[1], fbh[3]);
                }
                if (DO_LO) {
#pragma unroll
                    for (int mi = 0; mi < 2; mi++) {
                        mma16h(acc[mi][2 * njp],     fal[mi], fbh[0], fbh[2]);
                        mma16h(acc[mi][2 * njp + 1], fal[mi], fbh[1], fbh[3]);
                    }
                }
            }
        }
    }

    // epilogue (branch-free per MODE)
#pragma unroll
    for (int mi = 0; mi < 2; mi++) {
#pragma unroll
        for (int nj = 0; nj < 8; nj++) {
            int col = n0 + wn + nj * 8 + tg * 2;
#pragma unroll
            for (int half = 0; half < 2; half++) {
                int row = m0 + wm + mi * 16 + g + half * 8;
                float v0 = acc[mi][nj][half * 2], v1 = acc[mi][nj][half * 2 + 1];
                if (MODE == 0) {
                    C[(size_t)row * N + col]     = v0 + bias[col];
                    C[(size_t)row * N + col + 1] = v1 + bias[col + 1];
                } else if (MODE == 1) {
                    int bb = row >> 11, s2 = row & (S_ - 1);
                    int hh = col >> 7, d = col & 127;
                    size_t o = (((size_t)bb * NH_ + hh) * S_ + s2) * HD_ + d;
                    g_qf[o] = v0; g_qf[o + 1] = v1;
                } else {
                    int bb = row >> 11, s2 = row & (S_ - 1);
                    int kh = col >> 8, cc = col & 255;
                    if (cc < 128) {
                        size_t o = (((size_t)bb * NKV_ + kh) * S_ + s2) * HD_ + cc;
                        g_kf[o] = v0; g_kf[o + 1] = v1;
                    } else {
                        int d = cc - 128;
                        size_t o = (((size_t)bb * NKV_ + kh) * S_ + s2) * HD_ + d;
                        *(uint32_t*)(g_vh + o) = packh16(v0, v1);
                    }
                }
            }
        }
    }
}

// ---------------- RoPE + split (q -> f16 hi/lo, k -> f16) ----------------
__global__ void rope_split(const float* __restrict__ cosT, const float* __restrict__ sinT)
{
    int idx = blockIdx.x * blockDim.x + threadIdx.x;
    int d = idx & 63;
    int r = idx >> 6;
    int s = r & (S_ - 1);
    int hh = r >> 11;
    float c1 = cosT[s * HD_ + d],      s1 = sinT[s * HD_ + d];
    float c2 = cosT[s * HD_ + d + 64], s2 = sinT[s * HD_ + d + 64];
    if (hh < B_ * NH_) {
        const float* p = g_qf + (size_t)r * HD_;
        f16* oh = g_qh + (size_t)r * HD_;
        f16* ol = g_ql + (size_t)r * HD_;
        float x1 = p[d], x2 = p[d + 64];
        sstore16(oh, ol, d,      x1 * c1 - x2 * s1);
        sstore16(oh, ol, d + 64, x2 * c2 + x1 * s2);
    } else {
        size_t rr = (size_t)r - (size_t)B_ * NH_ * S_;
        const float* p = g_kf + rr * HD_;
        f16* ok = g_kh + rr * HD_;
        float x1 = p[d], x2 = p[d + 64];
        ok[d]      = __float2half_rn(x1 * c1 - x2 * s1);
        ok[d + 64] = __float2half_rn(x2 * c2 + x1 * s2);
    }
}

// ---------------- Flash attention, fp16 2-term ----------------
#define AQ 128
#define AK 64
#define RS_ 136
#define KVT (AK * RS_)
#define KVSTG (2 * KVT)
#define SBOFF (2 * AQ * RS_)
#define ASMEM ((SBOFF + 2 * KVSTG) * 2)

__global__ __launch_bounds__(256, 1) void attn_f16()
{
    extern __shared__ f16 smf[];
    f16* Qh = smf;
    f16* Ql = Qh + AQ * RS_;

    int qt = gridDim.x - 1 - blockIdx.x;
    int h = blockIdx.y, b = blockIdx.z;
    int tid = threadIdx.x, lane = tid & 31, wid = tid >> 5;
    int g = lane >> 2, tg = lane & 3;

    const f16* Qbh = g_qh + (((size_t)b * NH_ + h) * S_ + (size_t)qt * AQ) * HD_;
    const f16* Qbl = g_ql + (((size_t)b * NH_ + h) * S_ + (size_t)qt * AQ) * HD_;
    const f16* Kb  = g_kh + ((size_t)b * NKV_ + (h >> 2)) * S_ * HD_;
    const f16* Vb  = g_vh + ((size_t)b * NKV_ + (h >> 2)) * S_ * HD_;

#pragma unroll
    for (int i = 0; i < 8; i++) {
        int idx = tid + i * 256;
        int row = idx >> 4, q = idx & 15;
        size_t go = (size_t)row * HD_ + q * 8;
        cp16(&Qh[row * RS_ + q * 8], Qbh + go);
        cp16(&Ql[row * RS_ + q * 8], Qbl + go);
    }
    cp_commit();

    auto load_kv = [&](int kt, int s) {
        f16* base = smf + SBOFF + s * KVSTG;
#pragma unroll
        for (int i = 0; i < 4; i++) {
            int idx = tid + i * 256;
            int row = idx >> 4, q = idx & 15;
            size_t go = (size_t)(kt * AK + row) * HD_ + q * 8;
            int so = row * RS_ + q * 8;
            cp16(&base[so],       Kb + go);
            cp16(&base[KVT + so], Vb + go);
        }
    };

    float o[16][4];
#pragma unroll
    for (int j = 0; j < 16; j++)
#pragma unroll
        for (int c = 0; c < 4; c++) o[j][c] = 0.f;
    float m0 = -1e30f, m1 = -1e30f, l0 = 0.f, l1 = 0.f;
    const float scale = 0.08838834764831845f;
    int pr = wid * 16;

    int nkt = (qt + 1) * 2;
    load_kv(0, 0); cp_commit();

    for (int kt = 0; kt < nkt; kt++) {
        cp_wait0();
        __syncthreads();
        if (kt + 1 < nkt) { load_kv(kt + 1, (kt + 1) & 1); cp_commit(); }

        f16* Kh = smf + SBOFF + (kt & 1) * KVSTG;
        f16* Vh = Kh + KVT;

        float sf[8][4];
        uint32_t slo[8][2];
#pragma unroll
        for (int j = 0; j < 8; j++) {
            sf[j][0] = sf[j][1] = sf[j][2] = sf[j][3] = 0.f;
            slo[j][0] = slo[j][1] = 0u;
        }

#pragma unroll
        for (int k16 = 0; k16 < 8; k16++) {
            int kk = k16 * 16 + (lane >> 4) * 8;
            int aoff = (pr + (lane & 15)) * RS_ + kk;
            uint32_t fah[4], fal[4];
            ldsm4(fah, Qh + aoff);
            ldsm4(fal, Ql + aoff);
#pragma unroll
            for (int np2 = 0; np2 < 2; np2++) {
                uint32_t fb[2][4];
#pragma unroll
                for (int u = 0; u < 2; u++) {
                    int boff = ((np2 * 2 + u) * 16 + (lane & 15)) * RS_ + kk;
                    ldsm4(fb[u], Kh + boff);
                }
#pragma unroll
                for (int u = 0; u < 2; u++) {
                    int j = (np2 * 2 + u) * 2;
                    mma16h(sf[j],     fah, fb[u][0], fb[u][2]);
                    mma16h(sf[j + 1], fah, fb[u][1], fb[u][3]);
                }
#pragma unroll
                for (int u = 0; u < 2; u++) {
                    int j = (np2 * 2 + u) * 2;
                    mma16hh(slo[j],     fal, fb[u][0], fb[u][2]);
                    mma16hh(slo[j + 1], fal, fb[u][1], fb[u][3]);
                }
            }
        }
#pragma unroll
        for (int j = 0; j < 8; j++) {
            __half2 u0 = *reinterpret_cast<__half2*>(&slo[j][0]);
            __half2 u1 = *reinterpret_cast<__half2*>(&slo[j][1]);
            sf[j][0] += __low2float(u0);  sf[j][1] += __high2float(u0);
            sf[j][2] += __low2float(u1);  sf[j][3] += __high2float(u1);
        }

        int row0 = qt * AQ + wid * 16 + g;
        int colb = kt * AK + tg * 2;
        float mx0 = -1e30f, mx1 = -1e30f;
#pragma unroll
        for (int nj = 0; nj < 8; nj++) {
#pragma unroll
            for (int c = 0; c < 4; c++) {
                int col = colb + nj * 8 + (c & 1);
                int row = row0 + ((c & 2) ? 8 : 0);
                float v = sf[nj][c] * scale;
                if (col > row) v = -1e30f;
                sf[nj][c] = v;
                if (c < 2) mx0 = fmaxf(mx0, v); else mx1 = fmaxf(mx1, v);
            }
        }
        mx0 = fmaxf(mx0, __shfl_xor_sync(0xffffffffu, mx0, 1));
        mx0 = fmaxf(mx0, __shfl_xor_sync(0xffffffffu, mx0, 2));
        mx1 = fmaxf(mx1, __shfl_xor_sync(0xffffffffu, mx1, 1));
        mx1 = fmaxf(mx1, __shfl_xor_sync(0xffffffffu, mx1, 2));

        float mn0 = fmaxf(m0, mx0), mn1 = fmaxf(m1, mx1);
        float al0 = __expf(m0 - mn0), al1 = __expf(m1 - mn1);
        m0 = mn0; m1 = mn1;

        float rs0 = 0.f, rs1 = 0.f;
#pragma unroll
        for (int nj = 0; nj < 8; nj++) {
            float p0 = __expf(sf[nj][0] - mn0), p1 = __expf(sf[nj][1] - mn0);
            float p2 = __expf(sf[nj][2] - mn1), p3 = __expf(sf[nj][3] - mn1);
            sf[nj][0] = p0; sf[nj][1] = p1; sf[nj][2] = p2; sf[nj][3] = p3;
            rs0 += p0 + p1; rs1 += p2 + p3;
        }
        rs0 += __shfl_xor_sync(0xffffffffu, rs0, 1);
        rs0 += __shfl_xor_sync(0xffffffffu, rs0, 2);
        rs1 += __shfl_xor_sync(0xffffffffu, rs1, 1);
        rs1 += __shfl_xor_sync(0xffffffffu, rs1, 2);
        l0 = l0 * al0 + rs0;
        l1 = l1 * al1 + rs1;
#pragma unroll
        for (int j = 0; j < 16; j++) {
            o[j][0] *= al0; o[j][1] *= al0; o[j][2] *= al1; o[j][3] *= al1;
        }

#pragma unroll
        for (int t = 0; t < 4; t++) {
            uint32_t pah[4], pal[4];
            pah[0] = packh16(sf[2 * t][0], sf[2 * t][1]);
            pal[0] = packl16(sf[2 * t][0], sf[2 * t][1]);
            pah[1] = packh16(sf[2 * t][2], sf[2 * t][3]);
            pal[1] = packl16(sf[2 * t][2], sf[2 * t][3]);
            pah[2] = packh16(sf[2 * t + 1][0], sf[2 * t + 1][1]);
            pal[2] = packl16(sf[2 * t + 1][0], sf[2 * t + 1][1]);
            pah[3] = packh16(sf[2 * t + 1][2], sf[2 * t + 1][3]);
            pal[3] = packl16(sf[2 * t + 1][2], sf[2 * t + 1][3]);
#pragma unroll
            for (int dp = 0; dp < 4; dp++) {
                uint32_t fv[2][4];
#pragma unroll
                for (int u = 0; u < 2; u++) {
                    int dj = dp * 2 + u;
                    int voff = (t * 16 + (lane & 15)) * RS_ + dj * 16 + (lane >> 4) * 8;
                    ldsm4t(fv[u], Vh + voff);
                }
#pragma unroll
                for (int u = 0; u < 2; u++) {
                    int dj = dp * 2 + u;
                    mma16h(o[2 * dj],     pah, fv[u][0], fv[u][1]);
                    mma16h(o[2 * dj + 1], pah, fv[u][2], fv[u][3]);
                }
#pragma unroll
                for (int u = 0; u < 2; u++) {
                    int dj = dp * 2 + u;
                    mma16h(o[2 * dj],     pal, fv[u][0], fv[u][1]);
                    mma16h(o[2 * dj + 1], pal, fv[u][2], fv[u][3]);
                }
            }
        }
    }

    // epilogue: O/l -> ctx fp16 (hi only; GEMM2 is single-pass)
    float il0 = 1.f / l0, il1 = 1.f / l1;
    int row0 = qt * AQ + wid * 16 + g;
    size_t b0 = ((size_t)b * S_ + row0) * HID_ + (size_t)h * HD_;
    size_t b1 = b0 + (size_t)8 * HID_;
#pragma unroll
    for (int nj = 0; nj < 16; nj++) {
        int d = nj * 8 + tg * 2;
        *(uint32_t*)(g_ch + b0 + d) = packh16(o[nj][0] * il0, o[nj][1] * il0);
        *(uint32_t*)(g_ch + b1 + d) = packh16(o[nj][2] * il1, o[nj][3] * il1);
    }
}

// ---------------- launch ----------------
extern "C" void kernel_launch(void* const* d_in, const int* in_sizes, int n_in,
                              void* d_out, int out_size)
{
    const float* hs   = (const float*)d_in[0];
    const float* cosT = (const float*)d_in[2];
    const float* sinT = (const float*)d_in[3];
    const float* Wq   = (const float*)d_in[4];
    const float* Wkv  = (const float*)d_in[5];
    const float* Wd   = (const float*)d_in[6];
    const float* bd   = (const float*)d_in[7];
    float* out = (float*)d_out;

    cudaFuncSetAttribute(gemm_f16<1, true>,  cudaFuncAttributeMaxDynamicSharedMemorySize, GSMEM);
    cudaFuncSetAttribute(gemm_f16<2, false>, cudaFuncAttributeMaxDynamicSharedMemorySize, GSMEM);
    cudaFuncSetAttribute(gemm_f16<0, false>, cudaFuncAttributeMaxDynamicSharedMemorySize, GSMEM);
    cudaFuncSetAttribute(attn_f16, cudaFuncAttributeMaxDynamicSharedMemorySize, ASMEM);

    void *hsh, *hsl, *w, *wd, *ch;
    cudaGetSymbolAddress(&hsh, g_hsh);  cudaGetSymbolAddress(&hsl, g_hsl);
    cudaGetSymbolAddress(&w,   g_w);    cudaGetSymbolAddress(&wd,  g_wd);
    cudaGetSymbolAddress(&ch,  g_ch);

    const int total4 = (NHS_ + NWQ_ + NWKV_ + NWQ_) / 4;
    split4_kernel<<<total4 / 256, 256>>>(hs, Wq, Wkv, Wd);

    // GEMM1a: q columns, 2-pass (hi+lo)
    gemm_f16<1, true><<<dim3(HID_ / GBN, (B_ * S_) / GBM), 512, GSMEM>>>(
        (const f16*)hsh, (const f16*)hsl, (const f16*)w,
        bd, out, HID_, HID_);

    // GEMM1b: k/v columns, 1-pass
    gemm_f16<2, false><<<dim3((2 * NKV_ * HD_) / GBN, (B_ * S_) / GBM), 512, GSMEM>>>(
        (const f16*)hsh, (const f16*)hsh, (const f16*)w + (size_t)NWQ_,
        bd, out, HID_, HID_);

    rope_split<<<(B_ * (NH_ + NKV_) * S_ * 64) / 256, 256>>>(cosT, sinT);

    attn_f16<<<dim3(S_ / AQ, NH_, B_), 256, ASMEM>>>();

    // GEMM2: output projection + bias, 1-pass
    gemm_f16<0, false><<<dim3(HID_ / GBN, (B_ * S_) / GBM), 512, GSMEM>>>(
        (const f16*)ch, (const f16*)ch, (const f16*)wd,
        bd, out, HID_, HID_);
}

// round 14
// speedup vs baseline: 2.0930x; 1.2053x over previous
#include <cuda_runtime.h>
#include <cuda_fp16.h>
#include <cstdint>

#define B_   2
#define S_   2048
#define HID_ 4096
#define NH_  32
#define NKV_ 8
#define HD_  128

typedef __half f16;

// ---------------- device scratch ----------------
__device__ f16   g_hsh[(size_t)B_ * S_ * HID_];
__device__ f16   g_w  [(size_t)(HID_ + 2 * NKV_ * HD_) * HID_];
__device__ f16   g_wd [(size_t)HID_ * HID_];
__device__ float g_qf [(size_t)B_ * NH_ * S_ * HD_];
__device__ float g_kf [(size_t)B_ * NKV_ * S_ * HD_];
__device__ f16   g_qh [(size_t)B_ * NH_ * S_ * HD_];
__device__ f16   g_ql [(size_t)B_ * NH_ * S_ * HD_];
__device__ f16   g_kh [(size_t)B_ * NKV_ * S_ * HD_];
__device__ f16   g_vh [(size_t)B_ * NKV_ * S_ * HD_];
__device__ f16   g_ch [(size_t)B_ * S_ * HID_];

// ---------------- helpers ----------------
__device__ __forceinline__ void cp16(void* dst, const void* src) {
    unsigned d = (unsigned)__cvta_generic_to_shared(dst);
    asm volatile("cp.async.cg.shared.global [%0], [%1], 16;\n" :: "r"(d), "l"(src));
}
__device__ __forceinline__ void cp_commit() { asm volatile("cp.async.commit_group;\n"); }
__device__ __forceinline__ void cp_wait0()  { asm volatile("cp.async.wait_group 0;\n"); }
__device__ __forceinline__ void cp_wait1()  { asm volatile("cp.async.wait_group 1;\n"); }

__device__ __forceinline__ void ldsm4(uint32_t* r, const void* p) {
    uint32_t a = (uint32_t)__cvta_generic_to_shared(p);
    asm volatile("ldmatrix.sync.aligned.m8n8.x4.shared.b16 {%0,%1,%2,%3}, [%4];\n"
        : "=r"(r[0]), "=r"(r[1]), "=r"(r[2]), "=r"(r[3]) : "r"(a));
}
__device__ __forceinline__ void ldsm4t(uint32_t* r, const void* p) {
    uint32_t a = (uint32_t)__cvta_generic_to_shared(p);
    asm volatile("ldmatrix.sync.aligned.m8n8.x4.trans.shared.b16 {%0,%1,%2,%3}, [%4];\n"
        : "=r"(r[0]), "=r"(r[1]), "=r"(r[2]), "=r"(r[3]) : "r"(a));
}

__device__ __forceinline__ void mma16h(float* c, const uint32_t* a, uint32_t b0, uint32_t b1) {
    asm volatile(
        "mma.sync.aligned.m16n8k16.row.col.f32.f16.f16.f32 "
        "{%0,%1,%2,%3},{%4,%5,%6,%7},{%8,%9},{%0,%1,%2,%3};\n"
        : "+f"(c[0]), "+f"(c[1]), "+f"(c[2]), "+f"(c[3])
        : "r"(a[0]), "r"(a[1]), "r"(a[2]), "r"(a[3]), "r"(b0), "r"(b1));
}
__device__ __forceinline__ void mma16hh(uint32_t* c, const uint32_t* a, uint32_t b0, uint32_t b1) {
    asm volatile(
        "mma.sync.aligned.m16n8k16.row.col.f16.f16.f16.f16 "
        "{%0,%1},{%2,%3,%4,%5},{%6,%7},{%0,%1};\n"
        : "+r"(c[0]), "+r"(c[1])
        : "r"(a[0]), "r"(a[1]), "r"(a[2]), "r"(a[3]), "r"(b0), "r"(b1));
}

__device__ __forceinline__ uint32_t packh16(float e, float o) {
    __half2 t = __floats2half2_rn(e, o);
    return *reinterpret_cast<const uint32_t*>(&t);
}
__device__ __forceinline__ uint32_t packl16(float e, float o) {
    float he = __half2float(__float2half_rn(e));
    float ho = __half2float(__float2half_rn(o));
    return packh16(e - he, o - ho);
}
__device__ __forceinline__ void sstore16(f16* oh, f16* ol, int i, float v) {
    f16 h = __float2half_rn(v);
    oh[i] = h;
    ol[i] = __float2half_rn(v - __half2float(h));
}

// ---------------- fused split pass (fp32 -> fp16, no lo for hs) ----------
#define NHS_ (B_ * S_ * HID_)
#define NWQ_ (HID_ * HID_)
#define NWKV_ (2 * NKV_ * HD_ * HID_)

__global__ void split4_kernel(const float* __restrict__ hs, const float* __restrict__ Wq,
                              const float* __restrict__ Wkv, const float* __restrict__ Wd)
{
    int t = blockIdx.x * blockDim.x + threadIdx.x;
    const int q0 = NHS_ / 4, q1 = q0 + NWQ_ / 4, q2 = q1 + NWKV_ / 4;
    const float* src;
    f16* dst;
    int i;
    if (t < q0)      { src = hs;  dst = g_hsh;       i = t * 4; }
    else if (t < q1) { src = Wq;  dst = g_w;         i = (t - q0) * 4; }
    else if (t < q2) { src = Wkv; dst = g_w + NWQ_;  i = (t - q1) * 4; }
    else             { src = Wd;  dst = g_wd;        i = (t - q2) * 4; }
    float4 x = *(const float4*)(src + i);
    *(uint32_t*)(dst + i)     = packh16(x.x, x.y);
    *(uint32_t*)(dst + i + 2) = packh16(x.z, x.w);
}

// ------------- NT GEMM: 512 thr, 128x256x32, fp16 single-pass, 3-stage -------
// MODE 0: C[row*N+col] = acc + bias[col]
// MODE 1: scatter q (f32)
// MODE 2: scatter k (f32) / v (f16)
#define GBM 128
#define GBN 256
#define GBK 32
#define ARS 40
#define NSTG 3
#define AH_STG (GBM * ARS)
#define STGH ((GBM + GBN) * ARS)
#define GSMEM (NSTG * STGH * 2)

template<int MODE>
__global__ __launch_bounds__(512, 1) void gemm_f16(
    const f16* __restrict__ Ah,
    const f16* __restrict__ Wh,
    const float* __restrict__ bias, float* __restrict__ C,
    int N, int K)
{
    extern __shared__ f16 smh[];

    int tid = threadIdx.x, lane = tid & 31, wid = tid >> 5;
    int g = lane >> 2, tg = lane & 3;
    int wm = (wid & 3) << 5;
    int wn = (wid >> 2) << 6;
    int m0 = blockIdx.y * GBM, n0 = blockIdx.x * GBN;
    const f16* Abh = Ah + (size_t)m0 * K;
    const f16* Bbh = Wh + (size_t)n0 * K;

    float acc[2][8][4];
#pragma unroll
    for (int i = 0; i < 2; i++)
#pragma unroll
        for (int j = 0; j < 8; j++)
#pragma unroll
            for (int c = 0; c < 4; c++) acc[i][j][c] = 0.f;

    int nk = K / GBK;

    auto load_tile = [&](int kt, int s) {
        int k0 = kt * GBK;
        f16* ah = smh + s * STGH;
        f16* bh = ah + AH_STG;
        {
            int row = tid >> 2, q = tid & 3;
            size_t go = (size_t)row * K + k0 + q * 8;
            cp16(&ah[row * ARS + q * 8], Abh + go);
        }
#pragma unroll
        for (int i = 0; i < 2; i++) {
            int idx = tid + i * 512;
            int row = idx >> 2, q = idx & 3;
            size_t go = (size_t)row * K + k0 + q * 8;
            cp16(&bh[row * ARS + q * 8], Bbh + go);
        }
    };

    load_tile(0, 0); cp_commit();
    load_tile(1, 1); cp_commit();

    for (int kt = 0; kt < nk; kt++) {
        if (kt == nk - 1) cp_wait0(); else cp_wait1();
        __syncthreads();
        if (kt + 2 < nk) { load_tile(kt + 2, (kt + 2) % NSTG); cp_commit(); }

        int s = kt % NSTG;
        const f16* ah = smh + s * STGH;
        const f16* bh = ah + AH_STG;

#pragma unroll
        for (int k16 = 0; k16 < 2; k16++) {
            int kk = k16 * 16 + (lane >> 4) * 8;
            uint32_t fah[2][4];
#pragma unroll
            for (int mi = 0; mi < 2; mi++) {
                int aoff = (wm + mi * 16 + (lane & 15)) * ARS + kk;
                ldsm4(fah[mi], ah + aoff);
            }
#pragma unroll
            for (int njp = 0; njp < 4; njp++) {
                int boff = (wn + njp * 16 + (lane & 15)) * ARS + kk;
                uint32_t fbh[4];
                ldsm4(fbh, bh + boff);
#pragma unroll
                for (int mi = 0; mi < 2; mi++) {
                    mma16h(acc[mi][2 * njp],     fah[mi], fbh[0], fbh[2]);
                    mma16h(acc[mi][2 * njp + 1], fah[mi], fbh[1], fbh[3]);
                }
            }
        }
    }

    // epilogue (branch-free per MODE)
#pragma unroll
    for (int mi = 0; mi < 2; mi++) {
#pragma unroll
        for (int nj = 0; nj < 8; nj++) {
            int col = n0 + wn + nj * 8 + tg * 2;
#pragma unroll
            for (int half = 0; half < 2; half++) {
                int row = m0 + wm + mi * 16 + g + half * 8;
                float v0 = acc[mi][nj][half * 2], v1 = acc[mi][nj][half * 2 + 1];
                if (MODE == 0) {
                    C[(size_t)row * N + col]     = v0 + bias[col];
                    C[(size_t)row * N + col + 1] = v1 + bias[col + 1];
                } else if (MODE == 1) {
                    int bb = row >> 11, s2 = row & (S_ - 1);
                    int hh = col >> 7, d = col & 127;
                    size_t o = (((size_t)bb * NH_ + hh) * S_ + s2) * HD_ + d;
                    g_qf[o] = v0; g_qf[o + 1] = v1;
                } else {
                    int bb = row >> 11, s2 = row & (S_ - 1);
                    int kh = col >> 8, cc = col & 255;
                    if (cc < 128) {
                        size_t o = (((size_t)bb * NKV_ + kh) * S_ + s2) * HD_ + cc;
                        g_kf[o] = v0; g_kf[o + 1] = v1;
                    } else {
                        int d = cc - 128;
                        size_t o = (((size_t)bb * NKV_ + kh) * S_ + s2) * HD_ + d;
                        *(uint32_t*)(g_vh + o) = packh16(v0, v1);
                    }
                }
            }
        }
    }
}

// ---------------- RoPE + split (q -> f16 hi/lo, k -> f16) ----------------
__global__ void rope_split(const float* __restrict__ cosT, const float* __restrict__ sinT)
{
    int idx = blockIdx.x * blockDim.x + threadIdx.x;
    int d = idx & 63;
    int r = idx >> 6;
    int s = r & (S_ - 1);
    int hh = r >> 11;
    float c1 = cosT[s * HD_ + d],      s1 = sinT[s * HD_ + d];
    float c2 = cosT[s * HD_ + d + 64], s2 = sinT[s * HD_ + d + 64];
    if (hh < B_ * NH_) {
        const float* p = g_qf + (size_t)r * HD_;
        f16* oh = g_qh + (size_t)r * HD_;
        f16* ol = g_ql + (size_t)r * HD_;
        float x1 = p[d], x2 = p[d + 64];
        sstore16(oh, ol, d,      x1 * c1 - x2 * s1);
        sstore16(oh, ol, d + 64, x2 * c2 + x1 * s2);
    } else {
        size_t rr = (size_t)r - (size_t)B_ * NH_ * S_;
        const float* p = g_kf + rr * HD_;
        f16* ok = g_kh + rr * HD_;
        float x1 = p[d], x2 = p[d + 64];
        ok[d]      = __float2half_rn(x1 * c1 - x2 * s1);
        ok[d + 64] = __float2half_rn(x2 * c2 + x1 * s2);
    }
}

// ---------------- Flash attention, fp16 2-term ----------------
#define AQ 128
#define AK 64
#define RS_ 136
#define KVT (AK * RS_)
#define KVSTG (2 * KVT)
#define SBOFF (2 * AQ * RS_)
#define ASMEM ((SBOFF + 2 * KVSTG) * 2)

__global__ __launch_bounds__(256, 1) void attn_f16()
{
    extern __shared__ f16 smf[];
    f16* Qh = smf;
    f16* Ql = Qh + AQ * RS_;

    int qt = gridDim.x - 1 - blockIdx.x;
    int h = blockIdx.y, b = blockIdx.z;
    int tid = threadIdx.x, lane = tid & 31, wid = tid >> 5;
    int g = lane >> 2, tg = lane & 3;

    const f16* Qbh = g_qh + (((size_t)b * NH_ + h) * S_ + (size_t)qt * AQ) * HD_;
    const f16* Qbl = g_ql + (((size_t)b * NH_ + h) * S_ + (size_t)qt * AQ) * HD_;
    const f16* Kb  = g_kh + ((size_t)b * NKV_ + (h >> 2)) * S_ * HD_;
    const f16* Vb  = g_vh + ((size_t)b * NKV_ + (h >> 2)) * S_ * HD_;

#pragma unroll
    for (int i = 0; i < 8; i++) {
        int idx = tid + i * 256;
        int row = idx >> 4, q = idx & 15;
        size_t go = (size_t)row * HD_ + q * 8;
        cp16(&Qh[row * RS_ + q * 8], Qbh + go);
        cp16(&Ql[row * RS_ + q * 8], Qbl + go);
    }
    cp_commit();

    auto load_kv = [&](int kt, int s) {
        f16* base = smf + SBOFF + s * KVSTG;
#pragma unroll
        for (int i = 0; i < 4; i++) {
            int idx = tid + i * 256;
            int row = idx >> 4, q = idx & 15;
            size_t go = (size_t)(kt * AK + row) * HD_ + q * 8;
            int so = row * RS_ + q * 8;
            cp16(&base[so],       Kb + go);
            cp16(&base[KVT + so], Vb + go);
        }
    };

    float o[16][4];
#pragma unroll
    for (int j = 0; j < 16; j++)
#pragma unroll
        for (int c = 0; c < 4; c++) o[j][c] = 0.f;
    float m0 = -1e30f, m1 = -1e30f, l0 = 0.f, l1 = 0.f;
    const float scale = 0.08838834764831845f;
    int pr = wid * 16;

    int nkt = (qt + 1) * 2;
    load_kv(0, 0); cp_commit();

    for (int kt = 0; kt < nkt; kt++) {
        cp_wait0();
        __syncthreads();
        if (kt + 1 < nkt) { load_kv(kt + 1, (kt + 1) & 1); cp_commit(); }

        f16* Kh = smf + SBOFF + (kt & 1) * KVSTG;
        f16* Vh = Kh + KVT;

        float sf[8][4];
        uint32_t slo[8][2];
#pragma unroll
        for (int j = 0; j < 8; j++) {
            sf[j][0] = sf[j][1] = sf[j][2] = sf[j][3] = 0.f;
            slo[j][0] = slo[j][1] = 0u;
        }

#pragma unroll
        for (int k16 = 0; k16 < 8; k16++) {
            int kk = k16 * 16 + (lane >> 4) * 8;
            int aoff = (pr + (lane & 15)) * RS_ + kk;
            uint32_t fah[4], fal[4];
            ldsm4(fah, Qh + aoff);
            ldsm4(fal, Ql + aoff);
#pragma unroll
            for (int np2 = 0; np2 < 2; np2++) {
                uint32_t fb[2][4];
#pragma unroll
                for (int u = 0; u < 2; u++) {
                    int boff = ((np2 * 2 + u) * 16 + (lane & 15)) * RS_ + kk;
                    ldsm4(fb[u], Kh + boff);
                }
#pragma unroll
                for (int u = 0; u < 2; u++) {
                    int j = (np2 * 2 + u) * 2;
                    mma16h(sf[j],     fah, fb[u][0], fb[u][2]);
                    mma16h(sf[j + 1], fah, fb[u][1], fb[u][3]);
                }
#pragma unroll
                for (int u = 0; u < 2; u++) {
                    int j = (np2 * 2 + u) * 2;
                    mma16hh(slo[j],     fal, fb[u][0], fb[u][2]);
                    mma16hh(slo[j + 1], fal, fb[u][1], fb[u][3]);
                }
            }
        }
#pragma unroll
        for (int j = 0; j < 8; j++) {
            __half2 u0 = *reinterpret_cast<__half2*>(&slo[j][0]);
            __half2 u1 = *reinterpret_cast<__half2*>(&slo[j][1]);
            sf[j][0] += __low2float(u0);  sf[j][1] += __high2float(u0);
            sf[j][2] += __low2float(u1);  sf[j][3] += __high2float(u1);
        }

        int row0 = qt * AQ + wid * 16 + g;
        int colb = kt * AK + tg * 2;
        float mx0 = -1e30f, mx1 = -1e30f;
#pragma unroll
        for (int nj = 0; nj < 8; nj++) {
#pragma unroll
            for (int c = 0; c < 4; c++) {
                int col = colb + nj * 8 + (c & 1);
                int row = row0 + ((c & 2) ? 8 : 0);
                float v = sf[nj][c] * scale;
                if (col > row) v = -1e30f;
                sf[nj][c] = v;
                if (c < 2) mx0 = fmaxf(mx0, v); else mx1 = fmaxf(mx1, v);
            }
        }
        mx0 = fmaxf(mx0, __shfl_xor_sync(0xffffffffu, mx0, 1));
        mx0 = fmaxf(mx0, __shfl_xor_sync(0xffffffffu, mx0, 2));
        mx1 = fmaxf(mx1, __shfl_xor_sync(0xffffffffu, mx1, 1));
        mx1 = fmaxf(mx1, __shfl_xor_sync(0xffffffffu, mx1, 2));

        float mn0 = fmaxf(m0, mx0), mn1 = fmaxf(m1, mx1);
        float al0 = __expf(m0 - mn0), al1 = __expf(m1 - mn1);
        m0 = mn0; m1 = mn1;

        float rs0 = 0.f, rs1 = 0.f;
#pragma unroll
        for (int nj = 0; nj < 8; nj++) {
            float p0 = __expf(sf[nj][0] - mn0), p1 = __expf(sf[nj][1] - mn0);
            float p2 = __expf(sf[nj][2] - mn1), p3 = __expf(sf[nj][3] - mn1);
            sf[nj][0] = p0; sf[nj][1] = p1; sf[nj][2] = p2; sf[nj][3] = p3;
            rs0 += p0 + p1; rs1 += p2 + p3;
        }
        rs0 += __shfl_xor_sync(0xffffffffu, rs0, 1);
        rs0 += __shfl_xor_sync(0xffffffffu, rs0, 2);
        rs1 += __shfl_xor_sync(0xffffffffu, rs1, 1);
        rs1 += __shfl_xor_sync(0xffffffffu, rs1, 2);
        l0 = l0 * al0 + rs0;
        l1 = l1 * al1 + rs1;
#pragma unroll
        for (int j = 0; j < 16; j++) {
            o[j][0] *= al0; o[j][1] *= al0; o[j][2] *= al1; o[j][3] *= al1;
        }

#pragma unroll
        for (int t = 0; t < 4; t++) {
            uint32_t pah[4], pal[4];
            pah[0] = packh16(sf[2 * t][0], sf[2 * t][1]);
            pal[0] = packl16(sf[2 * t][0], sf[2 * t][1]);
            pah[1] = packh16(sf[2 * t][2], sf[2 * t][3]);
            pal[1] = packl16(sf[2 * t][2], sf[2 * t][3]);
            pah[2] = packh16(sf[2 * t + 1][0], sf[2 * t + 1][1]);
            pal[2] = packl16(sf[2 * t + 1][0], sf[2 * t + 1][1]);
            pah[3] = packh16(sf[2 * t + 1][2], sf[2 * t + 1][3]);
            pal[3] = packl16(sf[2 * t + 1][2], sf[2 * t + 1][3]);
#pragma unroll
            for (int dp = 0; dp < 4; dp++) {
                uint32_t fv[2][4];
#pragma unroll
                for (int u = 0; u < 2; u++) {
                    int dj = dp * 2 + u;
                    int voff = (t * 16 + (lane & 15)) * RS_ + dj * 16 + (lane >> 4) * 8;
                    ldsm4t(fv[u], Vh + voff);
                }
#pragma unroll
                for (int u = 0; u < 2; u++) {
                    int dj = dp * 2 + u;
                    mma16h(o[2 * dj],     pah, fv[u][0], fv[u][1]);
                    mma16h(o[2 * dj + 1], pah, fv[u][2], fv[u][3]);
                }
#pragma unroll
                for (int u = 0; u < 2; u++) {
                    int dj = dp * 2 + u;
                    mma16h(o[2 * dj],     pal, fv[u][0], fv[u][1]);
                    mma16h(o[2 * dj + 1], pal, fv[u][2], fv[u][3]);
                }
            }
        }
    }

    // epilogue: O/l -> ctx fp16 (hi only)
    float il0 = 1.f / l0, il1 = 1.f / l1;
    int row0 = qt * AQ + wid * 16 + g;
    size_t b0 = ((size_t)b * S_ + row0) * HID_ + (size_t)h * HD_;
    size_t b1 = b0 + (size_t)8 * HID_;
#pragma unroll
    for (int nj = 0; nj < 16; nj++) {
        int d = nj * 8 + tg * 2;
        *(uint32_t*)(g_ch + b0 + d) = packh16(o[nj][0] * il0, o[nj][1] * il0);
        *(uint32_t*)(g_ch + b1 + d) = packh16(o[nj][2] * il1, o[nj][3] * il1);
    }
}

// ---------------- launch ----------------
extern "C" void kernel_launch(void* const* d_in, const int* in_sizes, int n_in,
                              void* d_out, int out_size)
{
    const float* hs   = (const float*)d_in[0];
    const float* cosT = (const float*)d_in[2];
    const float* sinT = (const float*)d_in[3];
    const float* Wq   = (const float*)d_in[4];
    const float* Wkv  = (const float*)d_in[5];
    const float* Wd   = (const float*)d_in[6];
    const float* bd   = (const float*)d_in[7];
    float* out = (float*)d_out;

    cudaFuncSetAttribute(gemm_f16<0>, cudaFuncAttributeMaxDynamicSharedMemorySize, GSMEM);
    cudaFuncSetAttribute(gemm_f16<1>, cudaFuncAttributeMaxDynamicSharedMemorySize, GSMEM);
    cudaFuncSetAttribute(gemm_f16<2>, cudaFuncAttributeMaxDynamicSharedMemorySize, GSMEM);
    cudaFuncSetAttribute(attn_f16, cudaFuncAttributeMaxDynamicSharedMemorySize, ASMEM);

    void *hsh, *w, *wd, *ch;
    cudaGetSymbolAddress(&hsh, g_hsh);
    cudaGetSymbolAddress(&w,   g_w);    cudaGetSymbolAddress(&wd,  g_wd);
    cudaGetSymbolAddress(&ch,  g_ch);

    const int total4 = (NHS_ + NWQ_ + NWKV_ + NWQ_) / 4;
    split4_kernel<<<total4 / 256, 256>>>(hs, Wq, Wkv, Wd);

    // GEMM1a: q columns, single pass
    gemm_f16<1><<<dim3(HID_ / GBN, (B_ * S_) / GBM), 512, GSMEM>>>(
        (const f16*)hsh, (const f16*)w, bd, out, HID_, HID_);

    // GEMM1b: k/v columns, single pass
    gemm_f16<2><<<dim3((2 * NKV_ * HD_) / GBN, (B_ * S_) / GBM), 512, GSMEM>>>(
        (const f16*)hsh, (const f16*)w + (size_t)NWQ_, bd, out, HID_, HID_);

    rope_split<<<(B_ * (NH_ + NKV_) * S_ * 64) / 256, 256>>>(cosT, sinT);

    attn_f16<<<dim3(S_ / AQ, NH_, B_), 256, ASMEM>>>();

    // GEMM2: output projection + bias, single pass
    gemm_f16<0><<<dim3(HID_ / GBN, (B_ * S_) / GBM), 512, GSMEM>>>(
        (const f16*)ch, (const f16*)wd, bd, out, HID_, HID_);
}

// round 15
// speedup vs baseline: 2.1484x; 1.0265x over previous
#include <cuda_runtime.h>
#include <cuda_fp16.h>
#include <cstdint>

#define B_   2
#define S_   2048
#define HID_ 4096
#define NH_  32
#define NKV_ 8
#define HD_  128

typedef __half f16;

// ---------------- device scratch ----------------
__device__ f16   g_hsh[(size_t)B_ * S_ * HID_];
__device__ f16   g_w  [(size_t)(HID_ + 2 * NKV_ * HD_) * HID_];
__device__ f16   g_wd [(size_t)HID_ * HID_];
__device__ float g_qf [(size_t)B_ * NH_ * S_ * HD_];
__device__ float g_kf [(size_t)B_ * NKV_ * S_ * HD_];
__device__ f16   g_qh [(size_t)B_ * NH_ * S_ * HD_];
__device__ f16   g_kh [(size_t)B_ * NKV_ * S_ * HD_];
__device__ f16   g_vh [(size_t)B_ * NKV_ * S_ * HD_];
__device__ f16   g_ch [(size_t)B_ * S_ * HID_];

// ---------------- helpers ----------------
__device__ __forceinline__ void cp16(void* dst, const void* src) {
    unsigned d = (unsigned)__cvta_generic_to_shared(dst);
    asm volatile("cp.async.cg.shared.global [%0], [%1], 16;\n" :: "r"(d), "l"(src));
}
__device__ __forceinline__ void cp_commit() { asm volatile("cp.async.commit_group;\n"); }
__device__ __forceinline__ void cp_wait0()  { asm volatile("cp.async.wait_group 0;\n"); }
__device__ __forceinline__ void cp_wait1()  { asm volatile("cp.async.wait_group 1;\n"); }

__device__ __forceinline__ void ldsm4(uint32_t* r, const void* p) {
    uint32_t a = (uint32_t)__cvta_generic_to_shared(p);
    asm volatile("ldmatrix.sync.aligned.m8n8.x4.shared.b16 {%0,%1,%2,%3}, [%4];\n"
        : "=r"(r[0]), "=r"(r[1]), "=r"(r[2]), "=r"(r[3]) : "r"(a));
}
__device__ __forceinline__ void ldsm4t(uint32_t* r, const void* p) {
    uint32_t a = (uint32_t)__cvta_generic_to_shared(p);
    asm volatile("ldmatrix.sync.aligned.m8n8.x4.trans.shared.b16 {%0,%1,%2,%3}, [%4];\n"
        : "=r"(r[0]), "=r"(r[1]), "=r"(r[2]), "=r"(r[3]) : "r"(a));
}

__device__ __forceinline__ void mma16h(float* c, const uint32_t* a, uint32_t b0, uint32_t b1) {
    asm volatile(
        "mma.sync.aligned.m16n8k16.row.col.f32.f16.f16.f32 "
        "{%0,%1,%2,%3},{%4,%5,%6,%7},{%8,%9},{%0,%1,%2,%3};\n"
        : "+f"(c[0]), "+f"(c[1]), "+f"(c[2]), "+f"(c[3])
        : "r"(a[0]), "r"(a[1]), "r"(a[2]), "r"(a[3]), "r"(b0), "r"(b1));
}
__device__ __forceinline__ void mma16hh(uint32_t* c, const uint32_t* a, uint32_t b0, uint32_t b1) {
    asm volatile(
        "mma.sync.aligned.m16n8k16.row.col.f16.f16.f16.f16 "
        "{%0,%1},{%2,%3,%4,%5},{%6,%7},{%0,%1};\n"
        : "+r"(c[0]), "+r"(c[1])
        : "r"(a[0]), "r"(a[1]), "r"(a[2]), "r"(a[3]), "r"(b0), "r"(b1));
}

__device__ __forceinline__ uint32_t packh16(float e, float o) {
    __half2 t = __floats2half2_rn(e, o);
    return *reinterpret_cast<const uint32_t*>(&t);
}
__device__ __forceinline__ uint32_t packl16(float e, float o) {
    float he = __half2float(__float2half_rn(e));
    float ho = __half2float(__float2half_rn(o));
    return packh16(e - he, o - ho);
}

// ---------------- fused split pass (fp32 -> fp16) ----------
#define NHS_ (B_ * S_ * HID_)
#define NWQ_ (HID_ * HID_)
#define NWKV_ (2 * NKV_ * HD_ * HID_)

__global__ void split4_kernel(const float* __restrict__ hs, const float* __restrict__ Wq,
                              const float* __restrict__ Wkv, const float* __restrict__ Wd)
{
    int t = blockIdx.x * blockDim.x + threadIdx.x;
    const int q0 = NHS_ / 4, q1 = q0 + NWQ_ / 4, q2 = q1 + NWKV_ / 4;
    const float* src;
    f16* dst;
    int i;
    if (t < q0)      { src = hs;  dst = g_hsh;       i = t * 4; }
    else if (t < q1) { src = Wq;  dst = g_w;         i = (t - q0) * 4; }
    else if (t < q2) { src = Wkv; dst = g_w + NWQ_;  i = (t - q1) * 4; }
    else             { src = Wd;  dst = g_wd;        i = (t - q2) * 4; }
    float4 x = *(const float4*)(src + i);
    *(uint32_t*)(dst + i)     = packh16(x.x, x.y);
    *(uint32_t*)(dst + i + 2) = packh16(x.z, x.w);
}

// ------------- NT GEMM: 512 thr, 128x256x32, fp16 single-pass, 3-stage -------
#define GBM 128
#define GBN 256
#define GBK 32
#define ARS 40
#define NSTG 3
#define AH_STG (GBM * ARS)
#define STGH ((GBM + GBN) * ARS)
#define GSMEM (NSTG * STGH * 2)

template<int MODE>
__global__ __launch_bounds__(512, 1) void gemm_f16(
    const f16* __restrict__ Ah,
    const f16* __restrict__ Wh,
    const float* __restrict__ bias, float* __restrict__ C,
    int N, int K)
{
    extern __shared__ f16 smh[];

    int tid = threadIdx.x, lane = tid & 31, wid = tid >> 5;
    int g = lane >> 2, tg = lane & 3;
    int wm = (wid & 3) << 5;
    int wn = (wid >> 2) << 6;
    int m0 = blockIdx.y * GBM, n0 = blockIdx.x * GBN;
    const f16* Abh = Ah + (size_t)m0 * K;
    const f16* Bbh = Wh + (size_t)n0 * K;

    float acc[2][8][4];
#pragma unroll
    for (int i = 0; i < 2; i++)
#pragma unroll
        for (int j = 0; j < 8; j++)
#pragma unroll
            for (int c = 0; c < 4; c++) acc[i][j][c] = 0.f;

    int nk = K / GBK;

    auto load_tile = [&](int kt, int s) {
        int k0 = kt * GBK;
        f16* ah = smh + s * STGH;
        f16* bh = ah + AH_STG;
        {
            int row = tid >> 2, q = tid & 3;
            size_t go = (size_t)row * K + k0 + q * 8;
            cp16(&ah[row * ARS + q * 8], Abh + go);
        }
#pragma unroll
        for (int i = 0; i < 2; i++) {
            int idx = tid + i * 512;
            int row = idx >> 2, q = idx & 3;
            size_t go = (size_t)row * K + k0 + q * 8;
            cp16(&bh[row * ARS + q * 8], Bbh + go);
        }
    };

    load_tile(0, 0); cp_commit();
    load_tile(1, 1); cp_commit();

    for (int kt = 0; kt < nk; kt++) {
        if (kt == nk - 1) cp_wait0(); else cp_wait1();
        __syncthreads();
        if (kt + 2 < nk) { load_tile(kt + 2, (kt + 2) % NSTG); cp_commit(); }

        int s = kt % NSTG;
        const f16* ah = smh + s * STGH;
        const f16* bh = ah + AH_STG;

#pragma unroll
        for (int k16 = 0; k16 < 2; k16++) {
            int kk = k16 * 16 + (lane >> 4) * 8;
            uint32_t fah[2][4];
#pragma unroll
            for (int mi = 0; mi < 2; mi++) {
                int aoff = (wm + mi * 16 + (lane & 15)) * ARS + kk;
                ldsm4(fah[mi], ah + aoff);
            }
#pragma unroll
            for (int njp = 0; njp < 4; njp++) {
                int boff = (wn + njp * 16 + (lane & 15)) * ARS + kk;
                uint32_t fbh[4];
                ldsm4(fbh, bh + boff);
#pragma unroll
                for (int mi = 0; mi < 2; mi++) {
                    mma16h(acc[mi][2 * njp],     fah[mi], fbh[0], fbh[2]);
                    mma16h(acc[mi][2 * njp + 1], fah[mi], fbh[1], fbh[3]);
                }
            }
        }
    }

    // epilogue (branch-free per MODE)
#pragma unroll
    for (int mi = 0; mi < 2; mi++) {
#pragma unroll
        for (int nj = 0; nj < 8; nj++) {
            int col = n0 + wn + nj * 8 + tg * 2;
#pragma unroll
            for (int half = 0; half < 2; half++) {
                int row = m0 + wm + mi * 16 + g + half * 8;
                float v0 = acc[mi][nj][half * 2], v1 = acc[mi][nj][half * 2 + 1];
                if (MODE == 0) {
                    C[(size_t)row * N + col]     = v0 + bias[col];
                    C[(size_t)row * N + col + 1] = v1 + bias[col + 1];
                } else if (MODE == 1) {
                    int bb = row >> 11, s2 = row & (S_ - 1);
                    int hh = col >> 7, d = col & 127;
                    size_t o = (((size_t)bb * NH_ + hh) * S_ + s2) * HD_ + d;
                    g_qf[o] = v0; g_qf[o + 1] = v1;
                } else {
                    int bb = row >> 11, s2 = row & (S_ - 1);
                    int kh = col >> 8, cc = col & 255;
                    if (cc < 128) {
                        size_t o = (((size_t)bb * NKV_ + kh) * S_ + s2) * HD_ + cc;
                        g_kf[o] = v0; g_kf[o + 1] = v1;
                    } else {
                        int d = cc - 128;
                        size_t o = (((size_t)bb * NKV_ + kh) * S_ + s2) * HD_ + d;
                        *(uint32_t*)(g_vh + o) = packh16(v0, v1);
                    }
                }
            }
        }
    }
}

// ---------------- RoPE (q, k -> single f16) ----------------
__global__ void rope_split(const float* __restrict__ cosT, const float* __restrict__ sinT)
{
    int idx = blockIdx.x * blockDim.x + threadIdx.x;
    int d = idx & 63;
    int r = idx >> 6;
    int s = r & (S_ - 1);
    int hh = r >> 11;
    float c1 = cosT[s * HD_ + d],      s1 = sinT[s * HD_ + d];
    float c2 = cosT[s * HD_ + d + 64], s2 = sinT[s * HD_ + d + 64];
    const float* p;
    f16* od;
    if (hh < B_ * NH_) {
        p  = g_qf + (size_t)r * HD_;
        od = g_qh + (size_t)r * HD_;
    } else {
        size_t rr = (size_t)r - (size_t)B_ * NH_ * S_;
        p  = g_kf + rr * HD_;
        od = g_kh + rr * HD_;
    }
    float x1 = p[d], x2 = p[d + 64];
    od[d]      = __float2half_rn(x1 * c1 - x2 * s1);
    od[d + 64] = __float2half_rn(x2 * c2 + x1 * s2);
}

// ---------------- Flash attention: QK 1-term, PV hi f32 + lo f16acc ----------
#define AQ 128
#define AK 64
#define RS_ 136
#define KVT (AK * RS_)
#define KVSTG (2 * KVT)
#define SBOFF (AQ * RS_)
#define ASMEM ((SBOFF + 2 * KVSTG) * 2)   // 104448 bytes

__global__ __launch_bounds__(256, 1) void attn_f16()
{
    extern __shared__ f16 smf[];
    f16* Qh = smf;

    int qt = gridDim.x - 1 - blockIdx.x;
    int h = blockIdx.y, b = blockIdx.z;
    int tid = threadIdx.x, lane = tid & 31, wid = tid >> 5;
    int g = lane >> 2, tg = lane & 3;

    const f16* Qb = g_qh + (((size_t)b * NH_ + h) * S_ + (size_t)qt * AQ) * HD_;
    const f16* Kb = g_kh + ((size_t)b * NKV_ + (h >> 2)) * S_ * HD_;
    const f16* Vb = g_vh + ((size_t)b * NKV_ + (h >> 2)) * S_ * HD_;

#pragma unroll
    for (int i = 0; i < 8; i++) {
        int idx = tid + i * 256;
        int row = idx >> 4, q = idx & 15;
        cp16(&Qh[row * RS_ + q * 8], Qb + (size_t)row * HD_ + q * 8);
    }
    cp_commit();

    auto load_kv = [&](int kt, int s) {
        f16* base = smf + SBOFF + s * KVSTG;
#pragma unroll
        for (int i = 0; i < 4; i++) {
            int idx = tid + i * 256;
            int row = idx >> 4, q = idx & 15;
            size_t go = (size_t)(kt * AK + row) * HD_ + q * 8;
            int so = row * RS_ + q * 8;
            cp16(&base[so],       Kb + go);
            cp16(&base[KVT + so], Vb + go);
        }
    };

    float o[16][4];
#pragma unroll
    for (int j = 0; j < 16; j++)
#pragma unroll
        for (int c = 0; c < 4; c++) o[j][c] = 0.f;
    float m0 = -1e30f, m1 = -1e30f, l0 = 0.f, l1 = 0.f;
    const float scale = 0.08838834764831845f;
    int pr = wid * 16;

    int nkt = (qt + 1) * 2;
    load_kv(0, 0); cp_commit();

    for (int kt = 0; kt < nkt; kt++) {
        cp_wait0();
        __syncthreads();
        if (kt + 1 < nkt) { load_kv(kt + 1, (kt + 1) & 1); cp_commit(); }

        f16* Kh = smf + SBOFF + (kt & 1) * KVSTG;
        f16* Vh = Kh + KVT;

        // S = Q K^T (single fp16 term, f32 acc)
        float sf[8][4];
#pragma unroll
        for (int j = 0; j < 8; j++)
            sf[j][0] = sf[j][1] = sf[j][2] = sf[j][3] = 0.f;

#pragma unroll
        for (int k16 = 0; k16 < 8; k16++) {
            int kk = k16 * 16 + (lane >> 4) * 8;
            uint32_t fah[4];
            ldsm4(fah, Qh + (pr + (lane & 15)) * RS_ + kk);
#pragma unroll
            for (int np2 = 0; np2 < 2; np2++) {
                uint32_t fb[2][4];
#pragma unroll
                for (int u = 0; u < 2; u++) {
                    int boff = ((np2 * 2 + u) * 16 + (lane & 15)) * RS_ + kk;
                    ldsm4(fb[u], Kh + boff);
                }
#pragma unroll
                for (int u = 0; u < 2; u++) {
                    int j = (np2 * 2 + u) * 2;
                    mma16h(sf[j],     fah, fb[u][0], fb[u][2]);
                    mma16h(sf[j + 1], fah, fb[u][1], fb[u][3]);
                }
            }
        }

        int row0 = qt * AQ + wid * 16 + g;
        int colb = kt * AK + tg * 2;
        float mx0 = -1e30f, mx1 = -1e30f;
#pragma unroll
        for (int nj = 0; nj < 8; nj++) {
#pragma unroll
            for (int c = 0; c < 4; c++) {
                int col = colb + nj * 8 + (c & 1);
                int row = row0 + ((c & 2) ? 8 : 0);
                float v = sf[nj][c] * scale;
                if (col > row) v = -1e30f;
                sf[nj][c] = v;
                if (c < 2) mx0 = fmaxf(mx0, v); else mx1 = fmaxf(mx1, v);
            }
        }
        mx0 = fmaxf(mx0, __shfl_xor_sync(0xffffffffu, mx0, 1));
        mx0 = fmaxf(mx0, __shfl_xor_sync(0xffffffffu, mx0, 2));
        mx1 = fmaxf(mx1, __shfl_xor_sync(0xffffffffu, mx1, 1));
        mx1 = fmaxf(mx1, __shfl_xor_sync(0xffffffffu, mx1, 2));

        float mn0 = fmaxf(m0, mx0), mn1 = fmaxf(m1, mx1);
        float al0 = __expf(m0 - mn0), al1 = __expf(m1 - mn1);
        m0 = mn0; m1 = mn1;

        float rs0 = 0.f, rs1 = 0.f;
#pragma unroll
        for (int nj = 0; nj < 8; nj++) {
            float p0 = __expf(sf[nj][0] - mn0), p1 = __expf(sf[nj][1] - mn0);
            float p2 = __expf(sf[nj][2] - mn1), p3 = __expf(sf[nj][3] - mn1);
            sf[nj][0] = p0; sf[nj][1] = p1; sf[nj][2] = p2; sf[nj][3] = p3;
            rs0 += p0 + p1; rs1 += p2 + p3;
        }
        rs0 += __shfl_xor_sync(0xffffffffu, rs0, 1);
        rs0 += __shfl_xor_sync(0xffffffffu, rs0, 2);
        rs1 += __shfl_xor_sync(0xffffffffu, rs1, 1);
        rs1 += __shfl_xor_sync(0xffffffffu, rs1, 2);
        l0 = l0 * al0 + rs0;
        l1 = l1 * al1 + rs1;
#pragma unroll
        for (int j = 0; j < 16; j++) {
            o[j][0] *= al0; o[j][1] *= al0; o[j][2] *= al1; o[j][3] *= al1;
        }

        // O += P @ V: P hi (f32 acc) + P lo (f16 acc, folded per tile)
        uint32_t olo[16][2];
#pragma unroll
        for (int j = 0; j < 16; j++) { olo[j][0] = 0u; olo[j][1] = 0u; }

#pragma unroll
        for (int t = 0; t < 4; t++) {
            uint32_t pah[4], pal[4];
            pah[0] = packh16(sf[2 * t][0], sf[2 * t][1]);
            pal[0] = packl16(sf[2 * t][0], sf[2 * t][1]);
            pah[1] = packh16(sf[2 * t][2], sf[2 * t][3]);
            pal[1] = packl16(sf[2 * t][2], sf[2 * t][3]);
            pah[2] = packh16(sf[2 * t + 1][0], sf[2 * t + 1][1]);
            pal[2] = packl16(sf[2 * t + 1][0], sf[2 * t + 1][1]);
            pah[3] = packh16(sf[2 * t + 1][2], sf[2 * t + 1][3]);
            pal[3] = packl16(sf[2 * t + 1][2], sf[2 * t + 1][3]);
#pragma unroll
            for (int dp = 0; dp < 4; dp++) {
                uint32_t fv[2][4];
#pragma unroll
                for (int u = 0; u < 2; u++) {
                    int dj = dp * 2 + u;
                    int voff = (t * 16 + (lane & 15)) * RS_ + dj * 16 + (lane >> 4) * 8;
                    ldsm4t(fv[u], Vh + voff);
                }
#pragma unroll
                for (int u = 0; u < 2; u++) {
                    int dj = dp * 2 + u;
                    mma16h(o[2 * dj],     pah, fv[u][0], fv[u][1]);
                    mma16h(o[2 * dj + 1], pah, fv[u][2], fv[u][3]);
                }
#pragma unroll
                for (int u = 0; u < 2; u++) {
                    int dj = dp * 2 + u;
                    mma16hh(olo[2 * dj],     pal, fv[u][0], fv[u][1]);
                    mma16hh(olo[2 * dj + 1], pal, fv[u][2], fv[u][3]);
                }
            }
        }
        // fold f16-acc PV-lo into fp32 O
#pragma unroll
        for (int j = 0; j < 16; j++) {
            __half2 u0 = *reinterpret_cast<__half2*>(&olo[j][0]);
            __half2 u1 = *reinterpret_cast<__half2*>(&olo[j][1]);
            o[j][0] += __low2float(u0);  o[j][1] += __high2float(u0);
            o[j][2] += __low2float(u1);  o[j][3] += __high2float(u1);
        }
    }

    // epilogue: O/l -> ctx fp16
    float il0 = 1.f / l0, il1 = 1.f / l1;
    int row0 = qt * AQ + wid * 16 + g;
    size_t b0 = ((size_t)b * S_ + row0) * HID_ + (size_t)h * HD_;
    size_t b1 = b0 + (size_t)8 * HID_;
#pragma unroll
    for (int nj = 0; nj < 16; nj++) {
        int d = nj * 8 + tg * 2;
        *(uint32_t*)(g_ch + b0 + d) = packh16(o[nj][0] * il0, o[nj][1] * il0);
        *(uint32_t*)(g_ch + b1 + d) = packh16(o[nj][2] * il1, o[nj][3] * il1);
    }
}

// ---------------- launch ----------------
extern "C" void kernel_launch(void* const* d_in, const int* in_sizes, int n_in,
                              void* d_out, int out_size)
{
    const float* hs   = (const float*)d_in[0];
    const float* cosT = (const float*)d_in[2];
    const float* sinT = (const float*)d_in[3];
    const float* Wq   = (const float*)d_in[4];
    const float* Wkv  = (const float*)d_in[5];
    const float* Wd   = (const float*)d_in[6];
    const float* bd   = (const float*)d_in[7];
    float* out = (float*)d_out;

    cudaFuncSetAttribute(gemm_f16<0>, cudaFuncAttributeMaxDynamicSharedMemorySize, GSMEM);
    cudaFuncSetAttribute(gemm_f16<1>, cudaFuncAttributeMaxDynamicSharedMemorySize, GSMEM);
    cudaFuncSetAttribute(gemm_f16<2>, cudaFuncAttributeMaxDynamicSharedMemorySize, GSMEM);
    cudaFuncSetAttribute(attn_f16, cudaFuncAttributeMaxDynamicSharedMemorySize, ASMEM);

    void *hsh, *w, *wd, *ch;
    cudaGetSymbolAddress(&hsh, g_hsh);
    cudaGetSymbolAddress(&w,   g_w);    cudaGetSymbolAddress(&wd,  g_wd);
    cudaGetSymbolAddress(&ch,  g_ch);

    const int total4 = (NHS_ + NWQ_ + NWKV_ + NWQ_) / 4;
    split4_kernel<<<total4 / 256, 256>>>(hs, Wq, Wkv, Wd);

    // GEMM1a: q columns
    gemm_f16<1><<<dim3(HID_ / GBN, (B_ * S_) / GBM), 512, GSMEM>>>(
        (const f16*)hsh, (const f16*)w, bd, out, HID_, HID_);

    // GEMM1b: k/v columns
    gemm_f16<2><<<dim3((2 * NKV_ * HD_) / GBN, (B_ * S_) / GBM), 512, GSMEM>>>(
        (const f16*)hsh, (const f16*)w + (size_t)NWQ_, bd, out, HID_, HID_);

    rope_split<<<(B_ * (NH_ + NKV_) * S_ * 64) / 256, 256>>>(cosT, sinT);

    attn_f16<<<dim3(S_ / AQ, NH_, B_), 256, ASMEM>>>();

    // GEMM2: output projection + bias
    gemm_f16<0><<<dim3(HID_ / GBN, (B_ * S_) / GBM), 512, GSMEM>>>(
        (const f16*)ch, (const f16*)wd, bd, out, HID_, HID_);
}

// round 16
// speedup vs baseline: 2.2910x; 1.0664x over previous
#include <cuda_runtime.h>
#include <cuda_fp16.h>
#include <cstdint>

#define B_   2
#define S_   2048
#define HID_ 4096
#define NH_  32
#define NKV_ 8
#define HD_  128

typedef __half f16;

// ---------------- device scratch ----------------
__device__ f16   g_hsh[(size_t)B_ * S_ * HID_];
__device__ f16   g_w  [(size_t)(HID_ + 2 * NKV_ * HD_) * HID_];
__device__ f16   g_wd [(size_t)HID_ * HID_];
__device__ float g_qf [(size_t)B_ * NH_ * S_ * HD_];
__device__ float g_kf [(size_t)B_ * NKV_ * S_ * HD_];
__device__ f16   g_qh [(size_t)B_ * NH_ * S_ * HD_];
__device__ f16   g_kh [(size_t)B_ * NKV_ * S_ * HD_];
__device__ f16   g_vh [(size_t)B_ * NKV_ * S_ * HD_];
__device__ f16   g_ch [(size_t)B_ * S_ * HID_];

// ---------------- helpers ----------------
__device__ __forceinline__ void cp16(void* dst, const void* src) {
    unsigned d = (unsigned)__cvta_generic_to_shared(dst);
    asm volatile("cp.async.cg.shared.global [%0], [%1], 16;\n" :: "r"(d), "l"(src));
}
__device__ __forceinline__ void cp_commit() { asm volatile("cp.async.commit_group;\n"); }
__device__ __forceinline__ void cp_wait0()  { asm volatile("cp.async.wait_group 0;\n"); }
__device__ __forceinline__ void cp_wait1()  { asm volatile("cp.async.wait_group 1;\n"); }

__device__ __forceinline__ void ldsm4(uint32_t* r, const void* p) {
    uint32_t a = (uint32_t)__cvta_generic_to_shared(p);
    asm volatile("ldmatrix.sync.aligned.m8n8.x4.shared.b16 {%0,%1,%2,%3}, [%4];\n"
        : "=r"(r[0]), "=r"(r[1]), "=r"(r[2]), "=r"(r[3]) : "r"(a));
}
__device__ __forceinline__ void ldsm4t(uint32_t* r, const void* p) {
    uint32_t a = (uint32_t)__cvta_generic_to_shared(p);
    asm volatile("ldmatrix.sync.aligned.m8n8.x4.trans.shared.b16 {%0,%1,%2,%3}, [%4];\n"
        : "=r"(r[0]), "=r"(r[1]), "=r"(r[2]), "=r"(r[3]) : "r"(a));
}

__device__ __forceinline__ void mma16h(float* c, const uint32_t* a, uint32_t b0, uint32_t b1) {
    asm volatile(
        "mma.sync.aligned.m16n8k16.row.col.f32.f16.f16.f32 "
        "{%0,%1,%2,%3},{%4,%5,%6,%7},{%8,%9},{%0,%1,%2,%3};\n"
        : "+f"(c[0]), "+f"(c[1]), "+f"(c[2]), "+f"(c[3])
        : "r"(a[0]), "r"(a[1]), "r"(a[2]), "r"(a[3]), "r"(b0), "r"(b1));
}

__device__ __forceinline__ uint32_t packh16(float e, float o) {
    __half2 t = __floats2half2_rn(e, o);
    return *reinterpret_cast<const uint32_t*>(&t);
}

// ---------------- fused split pass (fp32 -> fp16) ----------
#define NHS_ (B_ * S_ * HID_)
#define NWQ_ (HID_ * HID_)
#define NWKV_ (2 * NKV_ * HD_ * HID_)

__global__ void split4_kernel(const float* __restrict__ hs, const float* __restrict__ Wq,
                              const float* __restrict__ Wkv, const float* __restrict__ Wd)
{
    int t = blockIdx.x * blockDim.x + threadIdx.x;
    const int q0 = NHS_ / 4, q1 = q0 + NWQ_ / 4, q2 = q1 + NWKV_ / 4;
    const float* src;
    f16* dst;
    int i;
    if (t < q0)      { src = hs;  dst = g_hsh;       i = t * 4; }
    else if (t < q1) { src = Wq;  dst = g_w;         i = (t - q0) * 4; }
    else if (t < q2) { src = Wkv; dst = g_w + NWQ_;  i = (t - q1) * 4; }
    else             { src = Wd;  dst = g_wd;        i = (t - q2) * 4; }
    float4 x = *(const float4*)(src + i);
    *(uint32_t*)(dst + i)     = packh16(x.x, x.y);
    *(uint32_t*)(dst + i + 2) = packh16(x.z, x.w);
}

// ------------- NT GEMM: 512 thr, 128x256x32, fp16 single-pass, 3-stage -------
#define GBM 128
#define GBN 256
#define GBK 32
#define ARS 40
#define NSTG 3
#define AH_STG (GBM * ARS)
#define STGH ((GBM + GBN) * ARS)
#define GSMEM (NSTG * STGH * 2)

template<int MODE>
__global__ __launch_bounds__(512, 1) void gemm_f16(
    const f16* __restrict__ Ah,
    const f16* __restrict__ Wh,
    const float* __restrict__ bias, float* __restrict__ C,
    int N, int K)
{
    extern __shared__ f16 smh[];

    int tid = threadIdx.x, lane = tid & 31, wid = tid >> 5;
    int g = lane >> 2, tg = lane & 3;
    int wm = (wid & 3) << 5;
    int wn = (wid >> 2) << 6;
    int m0 = blockIdx.y * GBM, n0 = blockIdx.x * GBN;
    const f16* Abh = Ah + (size_t)m0 * K;
    const f16* Bbh = Wh + (size_t)n0 * K;

    float acc[2][8][4];
#pragma unroll
    for (int i = 0; i < 2; i++)
#pragma unroll
        for (int j = 0; j < 8; j++)
#pragma unroll
            for (int c = 0; c < 4; c++) acc[i][j][c] = 0.f;

    int nk = K / GBK;

    auto load_tile = [&](int kt, int s) {
        int k0 = kt * GBK;
        f16* ah = smh + s * STGH;
        f16* bh = ah + AH_STG;
        {
            int row = tid >> 2, q = tid & 3;
            size_t go = (size_t)row * K + k0 + q * 8;
            cp16(&ah[row * ARS + q * 8], Abh + go);
        }
#pragma unroll
        for (int i = 0; i < 2; i++) {
            int idx = tid + i * 512;
            int row = idx >> 2, q = idx & 3;
            size_t go = (size_t)row * K + k0 + q * 8;
            cp16(&bh[row * ARS + q * 8], Bbh + go);
        }
    };

    load_tile(0, 0); cp_commit();
    load_tile(1, 1); cp_commit();

    for (int kt = 0; kt < nk; kt++) {
        if (kt == nk - 1) cp_wait0(); else cp_wait1();
        __syncthreads();
        if (kt + 2 < nk) { load_tile(kt + 2, (kt + 2) % NSTG); cp_commit(); }

        int s = kt % NSTG;
        const f16* ah = smh + s * STGH;
        const f16* bh = ah + AH_STG;

#pragma unroll
        for (int k16 = 0; k16 < 2; k16++) {
            int kk = k16 * 16 + (lane >> 4) * 8;
            uint32_t fah[2][4];
#pragma unroll
            for (int mi = 0; mi < 2; mi++) {
                int aoff = (wm + mi * 16 + (lane & 15)) * ARS + kk;
                ldsm4(fah[mi], ah + aoff);
            }
#pragma unroll
            for (int njp = 0; njp < 4; njp++) {
                int boff = (wn + njp * 16 + (lane & 15)) * ARS + kk;
                uint32_t fbh[4];
                ldsm4(fbh, bh + boff);
#pragma unroll
                for (int mi = 0; mi < 2; mi++) {
                    mma16h(acc[mi][2 * njp],     fah[mi], fbh[0], fbh[2]);
                    mma16h(acc[mi][2 * njp + 1], fah[mi], fbh[1], fbh[3]);
                }
            }
        }
    }

    // epilogue (branch-free per MODE)
#pragma unroll
    for (int mi = 0; mi < 2; mi++) {
#pragma unroll
        for (int nj = 0; nj < 8; nj++) {
            int col = n0 + wn + nj * 8 + tg * 2;
#pragma unroll
            for (int half = 0; half < 2; half++) {
                int row = m0 + wm + mi * 16 + g + half * 8;
                float v0 = acc[mi][nj][half * 2], v1 = acc[mi][nj][half * 2 + 1];
                if (MODE == 0) {
                    C[(size_t)row * N + col]     = v0 + bias[col];
                    C[(size_t)row * N + col + 1] = v1 + bias[col + 1];
                } else if (MODE == 1) {
                    int bb = row >> 11, s2 = row & (S_ - 1);
                    int hh = col >> 7, d = col & 127;
                    size_t o = (((size_t)bb * NH_ + hh) * S_ + s2) * HD_ + d;
                    g_qf[o] = v0; g_qf[o + 1] = v1;
                } else {
                    int bb = row >> 11, s2 = row & (S_ - 1);
                    int kh = col >> 8, cc = col & 255;
                    if (cc < 128) {
                        size_t o = (((size_t)bb * NKV_ + kh) * S_ + s2) * HD_ + cc;
                        g_kf[o] = v0; g_kf[o + 1] = v1;
                    } else {
                        int d = cc - 128;
                        size_t o = (((size_t)bb * NKV_ + kh) * S_ + s2) * HD_ + d;
                        *(uint32_t*)(g_vh + o) = packh16(v0, v1);
                    }
                }
            }
        }
    }
}

// ---------------- RoPE (q, k -> single f16) ----------------
__global__ void rope_split(const float* __restrict__ cosT, const float* __restrict__ sinT)
{
    int idx = blockIdx.x * blockDim.x + threadIdx.x;
    int d = idx & 63;
    int r = idx >> 6;
    int s = r & (S_ - 1);
    int hh = r >> 11;
    float c1 = cosT[s * HD_ + d],      s1 = sinT[s * HD_ + d];
    float c2 = cosT[s * HD_ + d + 64], s2 = sinT[s * HD_ + d + 64];
    const float* p;
    f16* od;
    if (hh < B_ * NH_) {
        p  = g_qf + (size_t)r * HD_;
        od = g_qh + (size_t)r * HD_;
    } else {
        size_t rr = (size_t)r - (size_t)B_ * NH_ * S_;
        p  = g_kf + rr * HD_;
        od = g_kh + rr * HD_;
    }
    float x1 = p[d], x2 = p[d + 64];
    od[d]      = __float2half_rn(x1 * c1 - x2 * s1);
    od[d + 64] = __float2half_rn(x2 * c2 + x1 * s2);
}

// ---------------- Flash attention: QK 1-term, PV 1-term (f32 acc) ------------
#define AQ 128
#define AK 64
#define RS_ 136
#define KVT (AK * RS_)
#define KVSTG (2 * KVT)
#define SBOFF (AQ * RS_)
#define ASMEM ((SBOFF + 2 * KVSTG) * 2)   // 104448 bytes

__global__ __launch_bounds__(256, 1) void attn_f16()
{
    extern __shared__ f16 smf[];
    f16* Qh = smf;

    int qt = gridDim.x - 1 - blockIdx.x;
    int h = blockIdx.y, b = blockIdx.z;
    int tid = threadIdx.x, lane = tid & 31, wid = tid >> 5;
    int g = lane >> 2, tg = lane & 3;

    const f16* Qb = g_qh + (((size_t)b * NH_ + h) * S_ + (size_t)qt * AQ) * HD_;
    const f16* Kb = g_kh + ((size_t)b * NKV_ + (h >> 2)) * S_ * HD_;
    const f16* Vb = g_vh + ((size_t)b * NKV_ + (h >> 2)) * S_ * HD_;

#pragma unroll
    for (int i = 0; i < 8; i++) {
        int idx = tid + i * 256;
        int row = idx >> 4, q = idx & 15;
        cp16(&Qh[row * RS_ + q * 8], Qb + (size_t)row * HD_ + q * 8);
    }
    cp_commit();

    auto load_kv = [&](int kt, int s) {
        f16* base = smf + SBOFF + s * KVSTG;
#pragma unroll
        for (int i = 0; i < 4; i++) {
            int idx = tid + i * 256;
            int row = idx >> 4, q = idx & 15;
            size_t go = (size_t)(kt * AK + row) * HD_ + q * 8;
            int so = row * RS_ + q * 8;
            cp16(&base[so],       Kb + go);
            cp16(&base[KVT + so], Vb + go);
        }
    };

    float o[16][4];
#pragma unroll
    for (int j = 0; j < 16; j++)
#pragma unroll
        for (int c = 0; c < 4; c++) o[j][c] = 0.f;
    float m0 = -1e30f, m1 = -1e30f, l0 = 0.f, l1 = 0.f;
    const float scale = 0.08838834764831845f;
    int pr = wid * 16;

    int nkt = (qt + 1) * 2;
    load_kv(0, 0); cp_commit();

    for (int kt = 0; kt < nkt; kt++) {
        cp_wait0();
        __syncthreads();
        if (kt + 1 < nkt) { load_kv(kt + 1, (kt + 1) & 1); cp_commit(); }

        f16* Kh = smf + SBOFF + (kt & 1) * KVSTG;
        f16* Vh = Kh + KVT;

        // S = Q K^T (single fp16 term, f32 acc)
        float sf[8][4];
#pragma unroll
        for (int j = 0; j < 8; j++)
            sf[j][0] = sf[j][1] = sf[j][2] = sf[j][3] = 0.f;

#pragma unroll
        for (int k16 = 0; k16 < 8; k16++) {
            int kk = k16 * 16 + (lane >> 4) * 8;
            uint32_t fah[4];
            ldsm4(fah, Qh + (pr + (lane & 15)) * RS_ + kk);
#pragma unroll
            for (int np2 = 0; np2 < 2; np2++) {
                uint32_t fb[2][4];
#pragma unroll
                for (int u = 0; u < 2; u++) {
                    int boff = ((np2 * 2 + u) * 16 + (lane & 15)) * RS_ + kk;
                    ldsm4(fb[u], Kh + boff);
                }
#pragma unroll
                for (int u = 0; u < 2; u++) {
                    int j = (np2 * 2 + u) * 2;
                    mma16h(sf[j],     fah, fb[u][0], fb[u][2]);
                    mma16h(sf[j + 1], fah, fb[u][1], fb[u][3]);
                }
            }
        }

        int row0 = qt * AQ + wid * 16 + g;
        int colb = kt * AK + tg * 2;
        float mx0 = -1e30f, mx1 = -1e30f;
#pragma unroll
        for (int nj = 0; nj < 8; nj++) {
#pragma unroll
            for (int c = 0; c < 4; c++) {
                int col = colb + nj * 8 + (c & 1);
                int row = row0 + ((c & 2) ? 8 : 0);
                float v = sf[nj][c] * scale;
                if (col > row) v = -1e30f;
                sf[nj][c] = v;
                if (c < 2) mx0 = fmaxf(mx0, v); else mx1 = fmaxf(mx1, v);
            }
        }
        mx0 = fmaxf(mx0, __shfl_xor_sync(0xffffffffu, mx0, 1));
        mx0 = fmaxf(mx0, __shfl_xor_sync(0xffffffffu, mx0, 2));
        mx1 = fmaxf(mx1, __shfl_xor_sync(0xffffffffu, mx1, 1));
        mx1 = fmaxf(mx1, __shfl_xor_sync(0xffffffffu, mx1, 2));

        float mn0 = fmaxf(m0, mx0), mn1 = fmaxf(m1, mx1);
        float al0 = __expf(m0 - mn0), al1 = __expf(m1 - mn1);
        m0 = mn0; m1 = mn1;

        float rs0 = 0.f, rs1 = 0.f;
#pragma unroll
        for (int nj = 0; nj < 8; nj++) {
            float p0 = __expf(sf[nj][0] - mn0), p1 = __expf(sf[nj][1] - mn0);
            float p2 = __expf(sf[nj][2] - mn1), p3 = __expf(sf[nj][3] - mn1);
            sf[nj][0] = p0; sf[nj][1] = p1; sf[nj][2] = p2; sf[nj][3] = p3;
            rs0 += p0 + p1; rs1 += p2 + p3;
        }
        rs0 += __shfl_xor_sync(0xffffffffu, rs0, 1);
        rs0 += __shfl_xor_sync(0xffffffffu, rs0, 2);
        rs1 += __shfl_xor_sync(0xffffffffu, rs1, 1);
        rs1 += __shfl_xor_sync(0xffffffffu, rs1, 2);
        l0 = l0 * al0 + rs0;
        l1 = l1 * al1 + rs1;
#pragma unroll
        for (int j = 0; j < 16; j++) {
            o[j][0] *= al0; o[j][1] *= al0; o[j][2] *= al1; o[j][3] *= al1;
        }

        // O += P @ V (single fp16 term, f32 acc)
#pragma unroll
        for (int t = 0; t < 4; t++) {
            uint32_t pah[4];
            pah[0] = packh16(sf[2 * t][0], sf[2 * t][1]);
            pah[1] = packh16(sf[2 * t][2], sf[2 * t][3]);
            pah[2] = packh16(sf[2 * t + 1][0], sf[2 * t + 1][1]);
            pah[3] = packh16(sf[2 * t + 1][2], sf[2 * t + 1][3]);
#pragma unroll
            for (int dp = 0; dp < 4; dp++) {
                uint32_t fv[2][4];
#pragma unroll
                for (int u = 0; u < 2; u++) {
                    int dj = dp * 2 + u;
                    int voff = (t * 16 + (lane & 15)) * RS_ + dj * 16 + (lane >> 4) * 8;
                    ldsm4t(fv[u], Vh + voff);
                }
#pragma unroll
                for (int u = 0; u < 2; u++) {
                    int dj = dp * 2 + u;
                    mma16h(o[2 * dj],     pah, fv[u][0], fv[u][1]);
                    mma16h(o[2 * dj + 1], pah, fv[u][2], fv[u][3]);
                }
            }
        }
    }

    // epilogue: O/l -> ctx fp16
    float il0 = 1.f / l0, il1 = 1.f / l1;
    int row0 = qt * AQ + wid * 16 + g;
    size_t b0 = ((size_t)b * S_ + row0) * HID_ + (size_t)h * HD_;
    size_t b1 = b0 + (size_t)8 * HID_;
#pragma unroll
    for (int nj = 0; nj < 16; nj++) {
        int d = nj * 8 + tg * 2;
        *(uint32_t*)(g_ch + b0 + d) = packh16(o[nj][0] * il0, o[nj][1] * il0);
        *(uint32_t*)(g_ch + b1 + d) = packh16(o[nj][2] * il1, o[nj][3] * il1);
    }
}

// ---------------- launch ----------------
extern "C" void kernel_launch(void* const* d_in, const int* in_sizes, int n_in,
                              void* d_out, int out_size)
{
    const float* hs   = (const float*)d_in[0];
    const float* cosT = (const float*)d_in[2];
    const float* sinT = (const float*)d_in[3];
    const float* Wq   = (const float*)d_in[4];
    const float* Wkv  = (const float*)d_in[5];
    const float* Wd   = (const float*)d_in[6];
    const float* bd   = (const float*)d_in[7];
    float* out = (float*)d_out;

    cudaFuncSetAttribute(gemm_f16<0>, cudaFuncAttributeMaxDynamicSharedMemorySize, GSMEM);
    cudaFuncSetAttribute(gemm_f16<1>, cudaFuncAttributeMaxDynamicSharedMemorySize, GSMEM);
    cudaFuncSetAttribute(gemm_f16<2>, cudaFuncAttributeMaxDynamicSharedMemorySize, GSMEM);
    cudaFuncSetAttribute(attn_f16, cudaFuncAttributeMaxDynamicSharedMemorySize, ASMEM);

    void *hsh, *w, *wd, *ch;
    cudaGetSymbolAddress(&hsh, g_hsh);
    cudaGetSymbolAddress(&w,   g_w);    cudaGetSymbolAddress(&wd,  g_wd);
    cudaGetSymbolAddress(&ch,  g_ch);

    const int total4 = (NHS_ + NWQ_ + NWKV_ + NWQ_) / 4;
    split4_kernel<<<total4 / 256, 256>>>(hs, Wq, Wkv, Wd);

    // GEMM1a: q columns
    gemm_f16<1><<<dim3(HID_ / GBN, (B_ * S_) / GBM), 512, GSMEM>>>(
        (const f16*)hsh, (const f16*)w, bd, out, HID_, HID_);

    // GEMM1b: k/v columns
    gemm_f16<2><<<dim3((2 * NKV_ * HD_) / GBN, (B_ * S_) / GBM), 512, GSMEM>>>(
        (const f16*)hsh, (const f16*)w + (size_t)NWQ_, bd, out, HID_, HID_);

    rope_split<<<(B_ * (NH_ + NKV_) * S_ * 64) / 256, 256>>>(cosT, sinT);

    attn_f16<<<dim3(S_ / AQ, NH_, B_), 256, ASMEM>>>();

    // GEMM2: output projection + bias
    gemm_f16<0><<<dim3(HID_ / GBN, (B_ * S_) / GBM), 512, GSMEM>>>(
        (const f16*)ch, (const f16*)wd, bd, out, HID_, HID_);
}